// round 2
// baseline (speedup 1.0000x reference)
#include <cuda_runtime.h>
#include <cstdint>

#define BATCH 64
#define VOCAB 50257
#define DIM   1024

// ---------------- scratch (static __device__, no allocs) ----------------
__device__ float g_logits[(size_t)BATCH * VOCAB];   // temp-scaled logits
__device__ float g_rowmax[BATCH];
__device__ float g_rowsum[BATCH];

// =========================================================================
// Kernel 0: zero the output buffer
// =========================================================================
__global__ void zero_kernel(float* out, int n) {
    int i = blockIdx.x * blockDim.x + threadIdx.x;
    int stride = gridDim.x * blockDim.x;
    for (; i < n; i += stride) out[i] = 0.0f;
}

// =========================================================================
// Kernel 1: logits = (H @ E^T) / temp   (fp32 SGEMM, M=64, N=50257, K=1024)
// =========================================================================
#define BM 64
#define BN 128
#define BKK 32

__global__ __launch_bounds__(256) void gemm_kernel(
    const float* __restrict__ H,      // [64, 1024]
    const float* __restrict__ E,      // [50257, 1024]
    const float* __restrict__ temps)  // [64]
{
    __shared__ float As[BKK][BM];        // [k][m]
    __shared__ float Bs[BKK][BN];        // [k][n]

    const int n0 = blockIdx.x * BN;
    const int t  = threadIdx.x;          // 0..255
    const int tx = t & 15;               // n group (16)
    const int ty = t >> 4;               // m group (16)

    float acc[4][8];
#pragma unroll
    for (int m = 0; m < 4; m++)
#pragma unroll
        for (int n = 0; n < 8; n++) acc[m][n] = 0.0f;

    for (int k0 = 0; k0 < DIM; k0 += BKK) {
        // load A tile 64x32 (512 float4, 2 per thread)
#pragma unroll
        for (int i = 0; i < 2; i++) {
            int idx = t + i * 256;
            int row = idx >> 3;          // /8  (8 float4 per 32-col row)
            int c4  = idx & 7;
            float4 a = *reinterpret_cast<const float4*>(H + row * DIM + k0 + c4 * 4);
            As[c4 * 4 + 0][row] = a.x;
            As[c4 * 4 + 1][row] = a.y;
            As[c4 * 4 + 2][row] = a.z;
            As[c4 * 4 + 3][row] = a.w;
        }
        // load B tile 128x32 (1024 float4, 4 per thread) with V guard
#pragma unroll
        for (int i = 0; i < 4; i++) {
            int idx = t + i * 256;
            int r   = idx >> 3;
            int c4  = idx & 7;
            int gn  = n0 + r;
            float4 b = make_float4(0.f, 0.f, 0.f, 0.f);
            if (gn < VOCAB)
                b = *reinterpret_cast<const float4*>(E + (size_t)gn * DIM + k0 + c4 * 4);
            Bs[c4 * 4 + 0][r] = b.x;
            Bs[c4 * 4 + 1][r] = b.y;
            Bs[c4 * 4 + 2][r] = b.z;
            Bs[c4 * 4 + 3][r] = b.w;
        }
        __syncthreads();

#pragma unroll
        for (int k = 0; k < BKK; k++) {
            float4 ra  = *reinterpret_cast<const float4*>(&As[k][ty * 4]);
            float4 rb0 = *reinterpret_cast<const float4*>(&Bs[k][tx * 8]);
            float4 rb1 = *reinterpret_cast<const float4*>(&Bs[k][tx * 8 + 4]);
            float ram[4] = {ra.x, ra.y, ra.z, ra.w};
            float rbn[8] = {rb0.x, rb0.y, rb0.z, rb0.w, rb1.x, rb1.y, rb1.z, rb1.w};
#pragma unroll
            for (int m = 0; m < 4; m++)
#pragma unroll
                for (int n = 0; n < 8; n++)
                    acc[m][n] = fmaf(ram[m], rbn[n], acc[m][n]);
        }
        __syncthreads();
    }

    // epilogue: divide by temperature, store
#pragma unroll
    for (int m = 0; m < 4; m++) {
        int gm = ty * 4 + m;
        float tmp = temps[gm];
#pragma unroll
        for (int n = 0; n < 8; n++) {
            int gn = n0 + tx * 8 + n;
            if (gn < VOCAB)
                g_logits[(size_t)gm * VOCAB + gn] = acc[m][n] / tmp;
        }
    }
}

// =========================================================================
// Kernel 2: per-row max and sum(exp(l - max))
// =========================================================================
__global__ __launch_bounds__(1024) void rowstats_kernel() {
    const int b = blockIdx.x;
    const int t = threadIdx.x;
    __shared__ float red[1024];
    __shared__ float smax;
    const float* row = g_logits + (size_t)b * VOCAB;

    float mx = -__int_as_float(0x7f800000);   // -inf
    for (int i = t; i < VOCAB; i += 1024) mx = fmaxf(mx, row[i]);
    red[t] = mx;
    __syncthreads();
    for (int s = 512; s > 0; s >>= 1) {
        if (t < s) red[t] = fmaxf(red[t], red[t + s]);
        __syncthreads();
    }
    if (t == 0) smax = red[0];
    __syncthreads();
    float lm = smax;

    float sum = 0.f;
    for (int i = t; i < VOCAB; i += 1024) sum += expf(row[i] - lm);
    red[t] = sum;
    __syncthreads();
    for (int s = 512; s > 0; s >>= 1) {
        if (t < s) red[t] += red[t + s];
        __syncthreads();
    }
    if (t == 0) {
        g_rowmax[b] = lm;
        g_rowsum[b] = red[0];
    }
}

// =========================================================================
// Kernel 3: top-k select, top-p/top-k filter, exact JAX categorical sample
// =========================================================================

__device__ __forceinline__ unsigned fmap(float f) {
    unsigned u = __float_as_uint(f);
    return (u & 0x80000000u) ? ~u : (u | 0x80000000u);
}
__device__ __forceinline__ float funmap(unsigned u) {
    unsigned b = (u & 0x80000000u) ? (u & 0x7fffffffu) : ~u;
    return __uint_as_float(b);
}

__device__ __forceinline__ unsigned rotl32(unsigned x, int r) {
    return (x << r) | (x >> (32 - r));
}

// jax threefry2x32, key = (0, 42)
__device__ __forceinline__ uint2 threefry_0_42(unsigned c0, unsigned c1) {
    const unsigned ks0 = 0u, ks1 = 42u;
    const unsigned ks2 = ks0 ^ ks1 ^ 0x1BD11BDAu;
    unsigned x0 = c0 + ks0;
    unsigned x1 = c1 + ks1;
#define TF_ROUND(r) { x0 += x1; x1 = rotl32(x1, r); x1 ^= x0; }
    // i = 0 (rot set A)
    TF_ROUND(13) TF_ROUND(15) TF_ROUND(26) TF_ROUND(6)
    x0 += ks1; x1 += ks2 + 1u;
    // i = 1 (rot set B)
    TF_ROUND(17) TF_ROUND(29) TF_ROUND(16) TF_ROUND(24)
    x0 += ks2; x1 += ks0 + 2u;
    // i = 2 (A)
    TF_ROUND(13) TF_ROUND(15) TF_ROUND(26) TF_ROUND(6)
    x0 += ks0; x1 += ks1 + 3u;
    // i = 3 (B)
    TF_ROUND(17) TF_ROUND(29) TF_ROUND(16) TF_ROUND(24)
    x0 += ks1; x1 += ks2 + 4u;
    // i = 4 (A)
    TF_ROUND(13) TF_ROUND(15) TF_ROUND(26) TF_ROUND(6)
    x0 += ks2; x1 += ks0 + 5u;
#undef TF_ROUND
    return make_uint2(x0, x1);
}

// gumbel noise for flat index i of a (B*V)-sized jax.random draw, key 42.
// PARTITIONABLE threefry layout (jax >= 0.4.36 default):
//   counts = iota(uint64); (b1,b2) = threefry(key, (hi32(i), lo32(i)));
//   bits32 = b1 ^ b2
__device__ __forceinline__ float jax_gumbel(unsigned i) {
    uint2 r = threefry_0_42(0u /* counts_hi */, i /* counts_lo */);
    unsigned bits = r.x ^ r.y;
    float f = __uint_as_float((bits >> 9) | 0x3f800000u) - 1.0f;
    float u = (f == 0.0f) ? 1.17549435e-38f : f;
    return -logf(-logf(u));
}

#define NCAND 2048
#define RANK  1000

__global__ __launch_bounds__(1024) void sample_kernel(
    const float* __restrict__ top_ps,
    const int*   __restrict__ top_ks,
    float* __restrict__ out_ids,
    float* __restrict__ out_lp,
    float* __restrict__ out_fprobs)
{
    const int b = blockIdx.x;
    const int t = threadIdx.x;
    const float* row = g_logits + (size_t)b * VOCAB;

    __shared__ unsigned long long s_keys[NCAND];
    __shared__ int   s_hist[2048];
    __shared__ float s_p[1024];
    __shared__ int   s_v[1024];
    __shared__ float s_rs[1024];
    __shared__ int   s_ri[1024];
    __shared__ int   s_sel1, s_rank2, s_sel2, s_cnt, s_m;

    // ---- pass 1: histogram of top 11 bits ----
    for (int i = t; i < 2048; i += 1024) s_hist[i] = 0;
    if (t == 0) s_cnt = 0;
    __syncthreads();
    for (int i = t; i < VOCAB; i += 1024) {
        unsigned k = fmap(row[i]);
        atomicAdd(&s_hist[k >> 21], 1);
    }
    __syncthreads();

    // warp 0: suffix-scan search for bin containing rank RANK
    if (t < 32) {
        int lane = t;
        int acc = 0;
        for (int base = 2048 - 32; base >= 0; base -= 32) {
            int bin = base + 31 - lane;          // lane 0 = highest bin in chunk
            int c = s_hist[bin];
            int p = c;
            for (int o = 1; o < 32; o <<= 1) {
                int v = __shfl_up_sync(0xffffffffu, p, o);
                if (lane >= o) p += v;
            }
            int S = acc + p;                     // count of keys in bins >= bin
            unsigned msk = __ballot_sync(0xffffffffu, S >= RANK);
            if (msk) {
                int l = __ffs(msk) - 1;
                int Ssel = __shfl_sync(0xffffffffu, S, l);
                int csel = __shfl_sync(0xffffffffu, c, l);
                if (lane == 0) {
                    s_sel1  = base + 31 - l;
                    s_rank2 = RANK - (Ssel - csel);  // remaining rank within bin
                }
                break;
            }
            acc += __shfl_sync(0xffffffffu, p, 31);
        }
    }
    __syncthreads();
    const int sel1 = s_sel1;
    const int rank2 = s_rank2;

    // ---- pass 2: histogram of next 11 bits within selected top bin ----
    for (int i = t; i < 2048; i += 1024) s_hist[i] = 0;
    __syncthreads();
    for (int i = t; i < VOCAB; i += 1024) {
        unsigned k = fmap(row[i]);
        if ((int)(k >> 21) == sel1)
            atomicAdd(&s_hist[(k >> 10) & 0x7FF], 1);
    }
    __syncthreads();

    if (t < 32) {
        int lane = t;
        int acc = 0;
        for (int base = 2048 - 32; base >= 0; base -= 32) {
            int bin = base + 31 - lane;
            int c = s_hist[bin];
            int p = c;
            for (int o = 1; o < 32; o <<= 1) {
                int v = __shfl_up_sync(0xffffffffu, p, o);
                if (lane >= o) p += v;
            }
            int S = acc + p;
            unsigned msk = __ballot_sync(0xffffffffu, S >= rank2);
            if (msk) {
                int l = __ffs(msk) - 1;
                if (lane == 0) s_sel2 = base + 31 - l;
                break;
            }
            acc += __shfl_sync(0xffffffffu, p, 31);
        }
    }
    __syncthreads();

    const unsigned Tkey = ((unsigned)sel1 << 21) | ((unsigned)s_sel2 << 10);

    // ---- pass 3: collect all keys >= Tkey ----
    for (int i = t; i < VOCAB; i += 1024) {
        unsigned k = fmap(row[i]);
        if (k >= Tkey) {
            int pos = atomicAdd(&s_cnt, 1);
            if (pos < NCAND)
                s_keys[pos] = ((unsigned long long)(~k) << 32) | (unsigned)i;
        }
    }
    __syncthreads();
    int cnt = s_cnt; if (cnt > NCAND) cnt = NCAND;
    for (int i = t; i < NCAND; i += 1024)
        if (i >= cnt) s_keys[i] = 0xFFFFFFFFFFFFFFFFull;
    __syncthreads();

    // ---- bitonic sort ascending (=> descending logit, stable tie by index) ----
    for (int k = 2; k <= NCAND; k <<= 1) {
        for (int j = k >> 1; j > 0; j >>= 1) {
            for (int i = t; i < NCAND; i += 1024) {
                int ixj = i ^ j;
                if (ixj > i) {
                    unsigned long long a = s_keys[i], c = s_keys[ixj];
                    bool asc = ((i & k) == 0);
                    if (asc ? (a > c) : (a < c)) {
                        s_keys[i] = c;
                        s_keys[ixj] = a;
                    }
                }
            }
            __syncthreads();
        }
    }

    // ---- serial top-p/top-k mask (monotone cumsum -> early exit) ----
    const float rmax = g_rowmax[b];
    const float rsum = g_rowsum[b];
    if (t == 0) {
        int   K  = top_ks[b];
        float tp = top_ps[b];
        int limit = cnt < K ? cnt : K;
        float cum = 0.f;
        int m = 0;
        for (int j = 0; j < limit; j++) {
            if (cum > tp) break;                 // (cumsum - p_j) > top_p => masked
            unsigned long long key = s_keys[j];
            unsigned hi = (unsigned)(key >> 32);
            float logit = funmap(~hi);
            int   idx   = (int)(unsigned)(key & 0xFFFFFFFFull);
            float p = expf(logit - rmax) / rsum;
            s_p[m] = p;
            s_v[m] = idx;
            m++;
            cum += p;
        }
        s_m = m;
    }
    __syncthreads();
    const int m = s_m;

    // ---- scatter fprobs + gumbel argmax over survivors ----
    float best  = -__int_as_float(0x7f800000);
    int   bestv = 0x7fffffff;
    for (int j = t; j < m; j += 1024) {
        int v = s_v[j];
        float p = s_p[j];
        out_fprobs[(size_t)b * VOCAB + v] = p;
        float g = jax_gumbel((unsigned)(b * VOCAB + v));
        float sc = logf(p) + g;
        if (sc > best || (sc == best && v < bestv)) { best = sc; bestv = v; }
    }
    s_rs[t] = best;
    s_ri[t] = bestv;
    __syncthreads();
    for (int s = 512; s > 0; s >>= 1) {
        if (t < s) {
            float o = s_rs[t + s]; int ov = s_ri[t + s];
            if (o > s_rs[t] || (o == s_rs[t] && ov < s_ri[t])) {
                s_rs[t] = o; s_ri[t] = ov;
            }
        }
        __syncthreads();
    }
    if (t == 0) {
        int tok = s_ri[0];
        out_ids[b] = (float)tok;
        float l = g_logits[(size_t)b * VOCAB + tok];
        out_lp[b] = l - rmax - logf(rsum);
    }
}

// =========================================================================
// launch
// =========================================================================
extern "C" void kernel_launch(void* const* d_in, const int* in_sizes, int n_in,
                              void* d_out, int out_size) {
    const float* H     = (const float*)d_in[0];   // hidden_states [64,1024]
    const float* E     = (const float*)d_in[1];   // embedding [50257,1024]
    const float* temps = (const float*)d_in[2];   // [64]
    const float* tps   = (const float*)d_in[3];   // [64]
    const int*   tks   = (const int*)d_in[4];     // [64]

    float* out = (float*)d_out;
    // layout [token_ids(64), token_logprobs(64), fprobs(64*50257)]
    int fbase = out_size - BATCH * VOCAB;
    if (fbase < 0) fbase = 0;
    float* out_ids = out;
    float* out_lp  = out + ((fbase >= 2 * BATCH) ? BATCH : 0);
    float* out_fp  = out + fbase;

    zero_kernel<<<512, 1024>>>(out, out_size);
    gemm_kernel<<<(VOCAB + BN - 1) / BN, 256>>>(H, E, temps);
    rowstats_kernel<<<BATCH, 1024>>>();
    sample_kernel<<<BATCH, 1024>>>(tps, tks, out_ids, out_lp, out_fp);
}

// round 4
// speedup vs baseline: 3.0662x; 3.0662x over previous
#include <cuda_runtime.h>
#include <cuda_bf16.h>
#include <cstdint>

#define BATCH 64
#define VOCAB 50257
#define VP    50304          /* padded row stride (393*128) */
#define DIM   1024

// ---------------- scratch (static __device__, no allocs) ----------------
__device__ float g_logits[(size_t)BATCH * VP];   // temp-scaled logits (padded rows)
__device__ float g_rowmax[BATCH];
__device__ float g_rowsum[BATCH];

// =========================================================================
// Kernel 0: zero the output buffer
// =========================================================================
__global__ void zero_kernel(float* out, int n) {
    int i = blockIdx.x * blockDim.x + threadIdx.x;
    int stride = gridDim.x * blockDim.x;
    for (; i < n; i += stride) out[i] = 0.0f;
}

// =========================================================================
// Kernel 1: HMMA bf16-split GEMM  (mma.sync — portable to compute_103 PTX)
//   logits[m,n] = (H[m,:] . E[n,:]) / temp[m],  M=64, N tiles of 128, K=1024
//   acc = Ahi*Bhi + Alo*Bhi + Ahi*Blo   (Alo*Blo ~2^-18, dropped)
// =========================================================================
#define TN   128
#define BK   32
#define NC   (DIM / BK)      /* 32 chunks */
#define SAST 40              /* smem row stride in bf16 elems (80B, conflict-free) */

__device__ __forceinline__ uint32_t smem_u32(const void* p) {
    uint32_t a;
    asm("{ .reg .u64 t; cvta.to.shared.u64 t, %1; cvt.u32.u64 %0, t; }" : "=r"(a) : "l"(p));
    return a;
}

#define LDMX4(d, addr)                                                            \
    asm volatile("ldmatrix.sync.aligned.m8n8.x4.shared.b16 {%0,%1,%2,%3}, [%4];"  \
        : "=r"((d)[0]), "=r"((d)[1]), "=r"((d)[2]), "=r"((d)[3]) : "r"(addr))

#define MMA16816(c, a, b0, b1)                                                    \
    asm volatile("mma.sync.aligned.m16n8k16.row.col.f32.bf16.bf16.f32 "           \
        "{%0,%1,%2,%3}, {%4,%5,%6,%7}, {%8,%9}, {%0,%1,%2,%3};"                   \
        : "+f"((c)[0]), "+f"((c)[1]), "+f"((c)[2]), "+f"((c)[3])                  \
        : "r"((a)[0]), "r"((a)[1]), "r"((a)[2]), "r"((a)[3]), "r"(b0), "r"(b1))

// float4 -> 4 bf16 hi (uint2) and 4 bf16 lo (uint2)
__device__ __forceinline__ void split4(float4 v, uint2& hi, uint2& lo) {
    __nv_bfloat16 h0 = __float2bfloat16(v.x), h1 = __float2bfloat16(v.y);
    __nv_bfloat16 h2 = __float2bfloat16(v.z), h3 = __float2bfloat16(v.w);
    __nv_bfloat16 l0 = __float2bfloat16(v.x - __bfloat162float(h0));
    __nv_bfloat16 l1 = __float2bfloat16(v.y - __bfloat162float(h1));
    __nv_bfloat16 l2 = __float2bfloat16(v.z - __bfloat162float(h2));
    __nv_bfloat16 l3 = __float2bfloat16(v.w - __bfloat162float(h3));
    hi.x = ((uint32_t)__bfloat16_as_ushort(h1) << 16) | __bfloat16_as_ushort(h0);
    hi.y = ((uint32_t)__bfloat16_as_ushort(h3) << 16) | __bfloat16_as_ushort(h2);
    lo.x = ((uint32_t)__bfloat16_as_ushort(l1) << 16) | __bfloat16_as_ushort(l0);
    lo.y = ((uint32_t)__bfloat16_as_ushort(l3) << 16) | __bfloat16_as_ushort(l2);
}

__global__ __launch_bounds__(256) void gemm_hmma_kernel(
    const float* __restrict__ H,      // [64, 1024]
    const float* __restrict__ E,      // [50257, 1024]
    const float* __restrict__ temps)  // [64]
{
    // A: rows 0-63 = hi, 64-127 = lo ; B: rows 0-127 = hi, 128-255 = lo
    __shared__ __align__(16) uint16_t sA[128 * SAST];
    __shared__ __align__(16) uint16_t sB[256 * SAST];

    const int t    = threadIdx.x;
    const int lane = t & 31;
    const int wid  = t >> 5;
    const int n0   = blockIdx.x * TN;
    const int wm   = (wid >> 2) * 32;      // warp m offset (0/32)
    const int wn   = (wid & 3) * 32;       // warp n offset (0/32/64/96)

    float acc[2][4][4];
#pragma unroll
    for (int i = 0; i < 2; i++)
#pragma unroll
        for (int j = 0; j < 4; j++)
#pragma unroll
            for (int k = 0; k < 4; k++) acc[i][j][k] = 0.0f;

    // per-thread load coordinates (A: 512 f4 -> 2/thread, B: 1024 f4 -> 4/thread)
    float4 ra[2], rb[4];

    auto loadG = [&](int c) {
        const int k0 = c * BK;
#pragma unroll
        for (int i = 0; i < 2; i++) {
            int idx = t + i * 256;
            int r = idx >> 3, c4 = idx & 7;
            ra[i] = __ldg(reinterpret_cast<const float4*>(H + r * DIM + k0 + c4 * 4));
        }
#pragma unroll
        for (int i = 0; i < 4; i++) {
            int idx = t + i * 256;
            int r = idx >> 3, c4 = idx & 7;
            int gn = n0 + r;
            rb[i] = (gn < VOCAB)
                ? __ldg(reinterpret_cast<const float4*>(E + (size_t)gn * DIM + k0 + c4 * 4))
                : make_float4(0.f, 0.f, 0.f, 0.f);
        }
    };
    auto storeS = [&]() {
#pragma unroll
        for (int i = 0; i < 2; i++) {
            int idx = t + i * 256;
            int r = idx >> 3, c4 = idx & 7;
            uint2 hi, lo;
            split4(ra[i], hi, lo);
            *reinterpret_cast<uint2*>(&sA[r * SAST + c4 * 4]) = hi;
            *reinterpret_cast<uint2*>(&sA[(r + 64) * SAST + c4 * 4]) = lo;
        }
#pragma unroll
        for (int i = 0; i < 4; i++) {
            int idx = t + i * 256;
            int r = idx >> 3, c4 = idx & 7;
            uint2 hi, lo;
            split4(rb[i], hi, lo);
            *reinterpret_cast<uint2*>(&sB[r * SAST + c4 * 4]) = hi;
            *reinterpret_cast<uint2*>(&sB[(r + 128) * SAST + c4 * 4]) = lo;
        }
    };

    const uint32_t aBase = smem_u32(sA);
    const uint32_t bBase = smem_u32(sB);
    const int rsel = (lane & 7) + ((lane >> 3) & 1) * 8;   // ldmatrix row select
    const int csel = (lane >> 4) * 8;                       // ldmatrix col select

    loadG(0);
    storeS();
    __syncthreads();

    for (int c = 0; c < NC; c++) {
        if (c + 1 < NC) loadG(c + 1);

        // compute chunk c: 2 k16 steps
#pragma unroll
        for (int ks = 0; ks < 2; ks++) {
            uint32_t af[2][2][4];   // [m-frag][hi/lo][4]
#pragma unroll
            for (int fm = 0; fm < 2; fm++)
#pragma unroll
                for (int h = 0; h < 2; h++) {
                    uint32_t addr = aBase +
                        (uint32_t)(((h * 64 + wm + fm * 16 + rsel) * SAST) + ks * 16 + csel) * 2;
                    LDMX4(af[fm][h], addr);
                }
            uint32_t bf[2][2][4];   // [n-pair][hi/lo][4]
#pragma unroll
            for (int np = 0; np < 2; np++)
#pragma unroll
                for (int h = 0; h < 2; h++) {
                    uint32_t addr = bBase +
                        (uint32_t)(((h * 128 + wn + np * 16 + rsel) * SAST) + ks * 16 + csel) * 2;
                    LDMX4(bf[np][h], addr);
                }
#pragma unroll
            for (int fm = 0; fm < 2; fm++)
#pragma unroll
                for (int fn = 0; fn < 4; fn++) {
                    int np = fn >> 1, sb = fn & 1;
                    MMA16816(acc[fm][fn], af[fm][0], bf[np][0][sb], bf[np][0][sb + 2]); // hi*hi
                    MMA16816(acc[fm][fn], af[fm][1], bf[np][0][sb], bf[np][0][sb + 2]); // lo*hi
                    MMA16816(acc[fm][fn], af[fm][0], bf[np][1][sb], bf[np][1][sb + 2]); // hi*lo
                }
        }
        __syncthreads();
        if (c + 1 < NC) {
            storeS();
            __syncthreads();
        }
    }

    // ---- epilogue: /temp, store (padded stride, unconditional) ----
#pragma unroll
    for (int fm = 0; fm < 2; fm++) {
        int m = wm + fm * 16 + (lane >> 2);
        float t0 = __ldg(temps + m);
        float t1 = __ldg(temps + m + 8);
#pragma unroll
        for (int fn = 0; fn < 4; fn++) {
            int n = n0 + wn + fn * 8 + (lane & 3) * 2;
            float2 v0 = make_float2(acc[fm][fn][0] / t0, acc[fm][fn][1] / t0);
            float2 v1 = make_float2(acc[fm][fn][2] / t1, acc[fm][fn][3] / t1);
            *reinterpret_cast<float2*>(&g_logits[(size_t)m * VP + n]) = v0;
            *reinterpret_cast<float2*>(&g_logits[(size_t)(m + 8) * VP + n]) = v1;
        }
    }
}

// =========================================================================
// Kernel 2: per-row max and sum(exp(l - max))
// =========================================================================
__global__ __launch_bounds__(1024) void rowstats_kernel() {
    const int b = blockIdx.x;
    const int t = threadIdx.x;
    __shared__ float red[1024];
    __shared__ float smax;
    const float* row = g_logits + (size_t)b * VP;

    float mx = -__int_as_float(0x7f800000);
    for (int i = t; i < VOCAB; i += 1024) mx = fmaxf(mx, row[i]);
    red[t] = mx;
    __syncthreads();
    for (int s = 512; s > 0; s >>= 1) {
        if (t < s) red[t] = fmaxf(red[t], red[t + s]);
        __syncthreads();
    }
    if (t == 0) smax = red[0];
    __syncthreads();
    float lm = smax;

    float sum = 0.f;
    for (int i = t; i < VOCAB; i += 1024) sum += expf(row[i] - lm);
    red[t] = sum;
    __syncthreads();
    for (int s = 512; s > 0; s >>= 1) {
        if (t < s) red[t] += red[t + s];
        __syncthreads();
    }
    if (t == 0) {
        g_rowmax[b] = lm;
        g_rowsum[b] = red[0];
    }
}

// =========================================================================
// Kernel 3: top-k select, top-p/top-k filter, exact JAX categorical sample
// =========================================================================
__device__ __forceinline__ unsigned fmap(float f) {
    unsigned u = __float_as_uint(f);
    return (u & 0x80000000u) ? ~u : (u | 0x80000000u);
}
__device__ __forceinline__ float funmap(unsigned u) {
    unsigned b = (u & 0x80000000u) ? (u & 0x7fffffffu) : ~u;
    return __uint_as_float(b);
}
__device__ __forceinline__ unsigned rotl32(unsigned x, int r) {
    return (x << r) | (x >> (32 - r));
}
// jax threefry2x32, key = (0, 42)
__device__ __forceinline__ uint2 threefry_0_42(unsigned c0, unsigned c1) {
    const unsigned ks0 = 0u, ks1 = 42u;
    const unsigned ks2 = ks0 ^ ks1 ^ 0x1BD11BDAu;
    unsigned x0 = c0 + ks0;
    unsigned x1 = c1 + ks1;
#define TF_ROUND(r) { x0 += x1; x1 = rotl32(x1, r); x1 ^= x0; }
    TF_ROUND(13) TF_ROUND(15) TF_ROUND(26) TF_ROUND(6)
    x0 += ks1; x1 += ks2 + 1u;
    TF_ROUND(17) TF_ROUND(29) TF_ROUND(16) TF_ROUND(24)
    x0 += ks2; x1 += ks0 + 2u;
    TF_ROUND(13) TF_ROUND(15) TF_ROUND(26) TF_ROUND(6)
    x0 += ks0; x1 += ks1 + 3u;
    TF_ROUND(17) TF_ROUND(29) TF_ROUND(16) TF_ROUND(24)
    x0 += ks1; x1 += ks2 + 4u;
    TF_ROUND(13) TF_ROUND(15) TF_ROUND(26) TF_ROUND(6)
    x0 += ks2; x1 += ks0 + 5u;
#undef TF_ROUND
    return make_uint2(x0, x1);
}
// partitionable threefry layout: bits = b1 ^ b2 of threefry(key, (0, i))
__device__ __forceinline__ float jax_gumbel(unsigned i) {
    uint2 r = threefry_0_42(0u, i);
    unsigned bits = r.x ^ r.y;
    float f = __uint_as_float((bits >> 9) | 0x3f800000u) - 1.0f;
    float u = (f == 0.0f) ? 1.17549435e-38f : f;
    return -logf(-logf(u));
}

#define NCAND 2048
#define RANK  1000

__global__ __launch_bounds__(1024) void sample_kernel(
    const float* __restrict__ top_ps,
    const int*   __restrict__ top_ks,
    float* __restrict__ out_ids,
    float* __restrict__ out_lp,
    float* __restrict__ out_fprobs)
{
    const int b = blockIdx.x;
    const int t = threadIdx.x;
    const int lane = t & 31;
    const int wid  = t >> 5;
    const float* row = g_logits + (size_t)b * VP;

    __shared__ unsigned long long s_keys[NCAND];
    __shared__ int   s_hist[2048];
    __shared__ float s_rs[1024];
    __shared__ int   s_ri[1024];
    __shared__ float s_wsum[32];
    __shared__ int   s_sel1, s_rank2, s_sel2, s_cnt;

    // ---- pass 1: histogram of top 11 bits ----
    for (int i = t; i < 2048; i += 1024) s_hist[i] = 0;
    if (t == 0) s_cnt = 0;
    __syncthreads();
    for (int i = t; i < VOCAB; i += 1024) {
        unsigned k = fmap(row[i]);
        atomicAdd(&s_hist[k >> 21], 1);
    }
    __syncthreads();

    if (t < 32) {
        int acc = 0;
        for (int base = 2048 - 32; base >= 0; base -= 32) {
            int bin = base + 31 - lane;
            int c = s_hist[bin];
            int p = c;
            for (int o = 1; o < 32; o <<= 1) {
                int v = __shfl_up_sync(0xffffffffu, p, o);
                if (lane >= o) p += v;
            }
            int S = acc + p;
            unsigned msk = __ballot_sync(0xffffffffu, S >= RANK);
            if (msk) {
                int l = __ffs(msk) - 1;
                int Ssel = __shfl_sync(0xffffffffu, S, l);
                int csel = __shfl_sync(0xffffffffu, c, l);
                if (lane == 0) {
                    s_sel1  = base + 31 - l;
                    s_rank2 = RANK - (Ssel - csel);
                }
                break;
            }
            acc += __shfl_sync(0xffffffffu, p, 31);
        }
    }
    __syncthreads();
    const int sel1 = s_sel1;
    const int rank2 = s_rank2;

    // ---- pass 2: histogram of next 11 bits within selected bin ----
    for (int i = t; i < 2048; i += 1024) s_hist[i] = 0;
    __syncthreads();
    for (int i = t; i < VOCAB; i += 1024) {
        unsigned k = fmap(row[i]);
        if ((int)(k >> 21) == sel1)
            atomicAdd(&s_hist[(k >> 10) & 0x7FF], 1);
    }
    __syncthreads();

    if (t < 32) {
        int acc = 0;
        for (int base = 2048 - 32; base >= 0; base -= 32) {
            int bin = base + 31 - lane;
            int c = s_hist[bin];
            int p = c;
            for (int o = 1; o < 32; o <<= 1) {
                int v = __shfl_up_sync(0xffffffffu, p, o);
                if (lane >= o) p += v;
            }
            int S = acc + p;
            unsigned msk = __ballot_sync(0xffffffffu, S >= rank2);
            if (msk) {
                int l = __ffs(msk) - 1;
                if (lane == 0) s_sel2 = base + 31 - l;
                break;
            }
            acc += __shfl_sync(0xffffffffu, p, 31);
        }
    }
    __syncthreads();

    const unsigned Tkey = ((unsigned)sel1 << 21) | ((unsigned)s_sel2 << 10);

    // ---- pass 3: collect keys >= Tkey ----
    for (int i = t; i < VOCAB; i += 1024) {
        unsigned k = fmap(row[i]);
        if (k >= Tkey) {
            int pos = atomicAdd(&s_cnt, 1);
            if (pos < NCAND)
                s_keys[pos] = ((unsigned long long)(~k) << 32) | (unsigned)i;
        }
    }
    __syncthreads();
    int cnt = s_cnt; if (cnt > NCAND) cnt = NCAND;
    for (int i = t; i < NCAND; i += 1024)
        if (i >= cnt) s_keys[i] = 0xFFFFFFFFFFFFFFFFull;
    __syncthreads();

    // ---- bitonic sort ascending (=> descending logit, stable ties) ----
    for (int k = 2; k <= NCAND; k <<= 1) {
        for (int j = k >> 1; j > 0; j >>= 1) {
            for (int i = t; i < NCAND; i += 1024) {
                int ixj = i ^ j;
                if (ixj > i) {
                    unsigned long long a = s_keys[i], c2 = s_keys[ixj];
                    bool asc = ((i & k) == 0);
                    if (asc ? (a > c2) : (a < c2)) {
                        s_keys[i] = c2;
                        s_keys[ixj] = a;
                    }
                }
            }
            __syncthreads();
        }
    }

    // ---- parallel top-p/top-k mask: survive iff rank<K && excl_cumsum<=tp ----
    const float rmax = g_rowmax[b];
    const float rsum = g_rowsum[b];
    const int   K    = top_ks[b];
    const float tp   = top_ps[b];
    const int limit  = (cnt < K ? cnt : K);      // K<=999 < 1024

    float p = 0.f;
    int   idx = 0;
    const bool valid = (t < limit);
    if (valid) {
        unsigned long long key = s_keys[t];
        unsigned hi = (unsigned)(key >> 32);
        float logit = funmap(~hi);
        idx = (int)(unsigned)(key & 0xFFFFFFFFull);
        p = expf(logit - rmax) / rsum;
    }
    // block-wide exclusive scan of p (1 elem/thread, 1024 threads)
    float x = p;
    for (int o = 1; o < 32; o <<= 1) {
        float v = __shfl_up_sync(0xffffffffu, x, o);
        if (lane >= o) x += v;
    }
    if (lane == 31) s_wsum[wid] = x;
    __syncthreads();
    if (wid == 0) {
        float w = s_wsum[lane];
        float y = w;
        for (int o = 1; o < 32; o <<= 1) {
            float v = __shfl_up_sync(0xffffffffu, y, o);
            if (lane >= o) y += v;
        }
        s_wsum[lane] = y - w;   // exclusive warp offsets
    }
    __syncthreads();
    float excl = s_wsum[wid] + x - p;
    const bool survive = valid && (excl <= tp);

    // ---- scatter fprobs + gumbel argmax over survivors ----
    float best  = -__int_as_float(0x7f800000);
    int   bestv = 0x7fffffff;
    if (survive) {
        out_fprobs[(size_t)b * VOCAB + idx] = p;
        float g = jax_gumbel((unsigned)(b * VOCAB + idx));
        best  = logf(p) + g;
        bestv = idx;
    }
    s_rs[t] = best;
    s_ri[t] = bestv;
    __syncthreads();
    for (int s = 512; s > 0; s >>= 1) {
        if (t < s) {
            float o = s_rs[t + s]; int ov = s_ri[t + s];
            if (o > s_rs[t] || (o == s_rs[t] && ov < s_ri[t])) {
                s_rs[t] = o; s_ri[t] = ov;
            }
        }
        __syncthreads();
    }
    if (t == 0) {
        int tok = s_ri[0];
        out_ids[b] = (float)tok;
        float l = g_logits[(size_t)b * VP + tok];
        out_lp[b] = l - rmax - logf(rsum);
    }
}

// =========================================================================
// launch
// =========================================================================
extern "C" void kernel_launch(void* const* d_in, const int* in_sizes, int n_in,
                              void* d_out, int out_size) {
    const float* H     = (const float*)d_in[0];
    const float* E     = (const float*)d_in[1];
    const float* temps = (const float*)d_in[2];
    const float* tps   = (const float*)d_in[3];
    const int*   tks   = (const int*)d_in[4];

    float* out = (float*)d_out;
    int fbase = out_size - BATCH * VOCAB;
    if (fbase < 0) fbase = 0;
    float* out_ids = out;
    float* out_lp  = out + ((fbase >= 2 * BATCH) ? BATCH : 0);
    float* out_fp  = out + fbase;

    zero_kernel<<<512, 1024>>>(out, out_size);
    gemm_hmma_kernel<<<(VOCAB + TN - 1) / TN, 256>>>(H, E, temps);
    rowstats_kernel<<<BATCH, 1024>>>();
    sample_kernel<<<BATCH, 1024>>>(tps, tks, out_ids, out_lp, out_fp);
}

// round 9
// speedup vs baseline: 3.2007x; 1.0439x over previous
#include <cuda_runtime.h>
#include <cuda_bf16.h>
#include <cstdint>

#define BATCH 64
#define VOCAB 50257
#define VP    50304          /* padded logits row stride (393*128) */
#define DIM   1024

// ---------------- scratch (static __device__, no allocs) ----------------
__device__ float g_logits[(size_t)BATCH * VP];

// =========================================================================
// Kernel 1: HMMA bf16-split GEMM, double-buffered smem
//   logits[m,n] = (H[m,:] . E[n,:]) / temp[m]
//   acc = Ahi*Bhi + Alo*Bhi + Ahi*Blo   (Alo*Blo ~2^-18, dropped)
// =========================================================================
#define TN   128
#define BK   32
#define NC   (DIM / BK)      /* 32 chunks */
#define SAST 40              /* smem row stride in bf16 elems (80B) */
#define ABUF (128 * SAST)    /* u16 elems per A buffer */
#define BBUF (256 * SAST)
#define BUFU16 (ABUF + BBUF) /* 15360 u16 = 30720 B */
#define GSMEM (2 * BUFU16 * 2)  /* 61440 B dynamic */

__device__ __forceinline__ uint32_t smem_u32(const void* p) {
    uint32_t a;
    asm("{ .reg .u64 t; cvta.to.shared.u64 t, %1; cvt.u32.u64 %0, t; }" : "=r"(a) : "l"(p));
    return a;
}

#define LDMX4(d, addr)                                                            \
    asm volatile("ldmatrix.sync.aligned.m8n8.x4.shared.b16 {%0,%1,%2,%3}, [%4];"  \
        : "=r"((d)[0]), "=r"((d)[1]), "=r"((d)[2]), "=r"((d)[3]) : "r"(addr))

#define MMA16816(c, a, b0, b1)                                                    \
    asm volatile("mma.sync.aligned.m16n8k16.row.col.f32.bf16.bf16.f32 "           \
        "{%0,%1,%2,%3}, {%4,%5,%6,%7}, {%8,%9}, {%0,%1,%2,%3};"                   \
        : "+f"((c)[0]), "+f"((c)[1]), "+f"((c)[2]), "+f"((c)[3])                  \
        : "r"((a)[0]), "r"((a)[1]), "r"((a)[2]), "r"((a)[3]), "r"(b0), "r"(b1))

__device__ __forceinline__ void split4(float4 v, uint2& hi, uint2& lo) {
    __nv_bfloat16 h0 = __float2bfloat16(v.x), h1 = __float2bfloat16(v.y);
    __nv_bfloat16 h2 = __float2bfloat16(v.z), h3 = __float2bfloat16(v.w);
    __nv_bfloat16 l0 = __float2bfloat16(v.x - __bfloat162float(h0));
    __nv_bfloat16 l1 = __float2bfloat16(v.y - __bfloat162float(h1));
    __nv_bfloat16 l2 = __float2bfloat16(v.z - __bfloat162float(h2));
    __nv_bfloat16 l3 = __float2bfloat16(v.w - __bfloat162float(h3));
    hi.x = ((uint32_t)__bfloat16_as_ushort(h1) << 16) | __bfloat16_as_ushort(h0);
    hi.y = ((uint32_t)__bfloat16_as_ushort(h3) << 16) | __bfloat16_as_ushort(h2);
    lo.x = ((uint32_t)__bfloat16_as_ushort(l1) << 16) | __bfloat16_as_ushort(l0);
    lo.y = ((uint32_t)__bfloat16_as_ushort(l3) << 16) | __bfloat16_as_ushort(l2);
}

__global__ __launch_bounds__(256) void gemm_hmma_kernel(
    const float* __restrict__ H,
    const float* __restrict__ E,
    const float* __restrict__ temps)
{
    extern __shared__ __align__(16) uint16_t dynsm[];

    const int t    = threadIdx.x;
    const int lane = t & 31;
    const int wid  = t >> 5;
    const int n0   = blockIdx.x * TN;
    const int wm   = (wid >> 2) * 32;
    const int wn   = (wid & 3) * 32;

    float acc[2][4][4];
#pragma unroll
    for (int i = 0; i < 2; i++)
#pragma unroll
        for (int j = 0; j < 4; j++)
#pragma unroll
            for (int k = 0; k < 4; k++) acc[i][j][k] = 0.0f;

    float4 ra[2], rb[4];

    auto loadG = [&](int c) {
        const int k0 = c * BK;
#pragma unroll
        for (int i = 0; i < 2; i++) {
            int idx = t + i * 256;
            int r = idx >> 3, c4 = idx & 7;
            ra[i] = __ldg(reinterpret_cast<const float4*>(H + r * DIM + k0 + c4 * 4));
        }
#pragma unroll
        for (int i = 0; i < 4; i++) {
            int idx = t + i * 256;
            int r = idx >> 3, c4 = idx & 7;
            int gn = n0 + r;
            rb[i] = (gn < VOCAB)
                ? __ldg(reinterpret_cast<const float4*>(E + (size_t)gn * DIM + k0 + c4 * 4))
                : make_float4(0.f, 0.f, 0.f, 0.f);
        }
    };
    auto storeS = [&](int buf) {
        uint16_t* sA = dynsm + buf * BUFU16;
        uint16_t* sB = sA + ABUF;
#pragma unroll
        for (int i = 0; i < 2; i++) {
            int idx = t + i * 256;
            int r = idx >> 3, c4 = idx & 7;
            uint2 hi, lo;
            split4(ra[i], hi, lo);
            *reinterpret_cast<uint2*>(&sA[r * SAST + c4 * 4]) = hi;
            *reinterpret_cast<uint2*>(&sA[(r + 64) * SAST + c4 * 4]) = lo;
        }
#pragma unroll
        for (int i = 0; i < 4; i++) {
            int idx = t + i * 256;
            int r = idx >> 3, c4 = idx & 7;
            uint2 hi, lo;
            split4(rb[i], hi, lo);
            *reinterpret_cast<uint2*>(&sB[r * SAST + c4 * 4]) = hi;
            *reinterpret_cast<uint2*>(&sB[(r + 128) * SAST + c4 * 4]) = lo;
        }
    };

    const uint32_t dynBase = smem_u32(dynsm);
    const int rsel = (lane & 7) + ((lane >> 3) & 1) * 8;
    const int csel = (lane >> 4) * 8;

    loadG(0);
    storeS(0);
    __syncthreads();

    for (int c = 0; c < NC; c++) {
        if (c + 1 < NC) loadG(c + 1);

        const uint32_t aBase = dynBase + (uint32_t)(c & 1) * (BUFU16 * 2);
        const uint32_t bBase = aBase + ABUF * 2;
#pragma unroll
        for (int ks = 0; ks < 2; ks++) {
            uint32_t af[2][2][4];
#pragma unroll
            for (int fm = 0; fm < 2; fm++)
#pragma unroll
                for (int h = 0; h < 2; h++) {
                    uint32_t addr = aBase +
                        (uint32_t)(((h * 64 + wm + fm * 16 + rsel) * SAST) + ks * 16 + csel) * 2;
                    LDMX4(af[fm][h], addr);
                }
            uint32_t bf[2][2][4];
#pragma unroll
            for (int np = 0; np < 2; np++)
#pragma unroll
                for (int h = 0; h < 2; h++) {
                    uint32_t addr = bBase +
                        (uint32_t)(((h * 128 + wn + np * 16 + rsel) * SAST) + ks * 16 + csel) * 2;
                    LDMX4(bf[np][h], addr);
                }
#pragma unroll
            for (int fm = 0; fm < 2; fm++)
#pragma unroll
                for (int fn = 0; fn < 4; fn++) {
                    int np = fn >> 1, sb = fn & 1;
                    MMA16816(acc[fm][fn], af[fm][0], bf[np][0][sb], bf[np][0][sb + 2]); // hi*hi
                    MMA16816(acc[fm][fn], af[fm][1], bf[np][0][sb], bf[np][0][sb + 2]); // lo*hi
                    MMA16816(acc[fm][fn], af[fm][0], bf[np][1][sb], bf[np][1][sb + 2]); // hi*lo
                }
        }
        if (c + 1 < NC) storeS((c + 1) & 1);
        __syncthreads();
    }

    // ---- epilogue: /temp, store (padded stride, unconditional) ----
#pragma unroll
    for (int fm = 0; fm < 2; fm++) {
        int m = wm + fm * 16 + (lane >> 2);
        float t0 = __ldg(temps + m);
        float t1 = __ldg(temps + m + 8);
#pragma unroll
        for (int fn = 0; fn < 4; fn++) {
            int n = n0 + wn + fn * 8 + (lane & 3) * 2;
            float2 v0 = make_float2(acc[fm][fn][0] / t0, acc[fm][fn][1] / t0);
            float2 v1 = make_float2(acc[fm][fn][2] / t1, acc[fm][fn][3] / t1);
            *reinterpret_cast<float2*>(&g_logits[(size_t)m * VP + n]) = v0;
            *reinterpret_cast<float2*>(&g_logits[(size_t)(m + 8) * VP + n]) = v1;
        }
    }
}

// =========================================================================
// Kernel 2: fused softmax-stats + top-k select + top-p/top-k + JAX sample
// =========================================================================
__device__ __forceinline__ unsigned fmap(float f) {
    unsigned u = __float_as_uint(f);
    return (u & 0x80000000u) ? ~u : (u | 0x80000000u);
}
__device__ __forceinline__ float funmap(unsigned u) {
    unsigned b = (u & 0x80000000u) ? (u & 0x7fffffffu) : ~u;
    return __uint_as_float(b);
}
__device__ __forceinline__ unsigned rotl32(unsigned x, int r) {
    return (x << r) | (x >> (32 - r));
}
// jax threefry2x32, key = (0, 42)
__device__ __forceinline__ uint2 threefry_0_42(unsigned c0, unsigned c1) {
    const unsigned ks0 = 0u, ks1 = 42u;
    const unsigned ks2 = ks0 ^ ks1 ^ 0x1BD11BDAu;
    unsigned x0 = c0 + ks0;
    unsigned x1 = c1 + ks1;
#define TF_ROUND(r) { x0 += x1; x1 = rotl32(x1, r); x1 ^= x0; }
    TF_ROUND(13) TF_ROUND(15) TF_ROUND(26) TF_ROUND(6)
    x0 += ks1; x1 += ks2 + 1u;
    TF_ROUND(17) TF_ROUND(29) TF_ROUND(16) TF_ROUND(24)
    x0 += ks2; x1 += ks0 + 2u;
    TF_ROUND(13) TF_ROUND(15) TF_ROUND(26) TF_ROUND(6)
    x0 += ks0; x1 += ks1 + 3u;
    TF_ROUND(17) TF_ROUND(29) TF_ROUND(16) TF_ROUND(24)
    x0 += ks1; x1 += ks2 + 4u;
    TF_ROUND(13) TF_ROUND(15) TF_ROUND(26) TF_ROUND(6)
    x0 += ks2; x1 += ks0 + 5u;
#undef TF_ROUND
    return make_uint2(x0, x1);
}
// partitionable threefry layout: bits = b1 ^ b2 of threefry(key, (0, i))
__device__ __forceinline__ float jax_gumbel(unsigned i) {
    uint2 r = threefry_0_42(0u, i);
    unsigned bits = r.x ^ r.y;
    float f = __uint_as_float((bits >> 9) | 0x3f800000u) - 1.0f;
    float u = (f == 0.0f) ? 1.17549435e-38f : f;
    return -logf(-logf(u));
}

#define NCAND 2048
#define RANK  1000
#define NF4   12565          /* ceil(VOCAB/4); reads stay inside VP padding */

__global__ __launch_bounds__(1024) void sample_kernel(
    const float* __restrict__ top_ps,
    const int*   __restrict__ top_ks,
    float* __restrict__ out_ids,
    float* __restrict__ out_lp,
    float* __restrict__ out_fprobs)
{
    const int b    = blockIdx.x;
    const int t    = threadIdx.x;
    const int lane = t & 31;
    const int wid  = t >> 5;
    const float* row = g_logits + (size_t)b * VP;
    const float4* row4 = reinterpret_cast<const float4*>(row);
    float* fp = out_fprobs + (size_t)b * VOCAB;

    __shared__ unsigned long long s_keys[NCAND];
    __shared__ unsigned long long s_sel[NCAND];
    __shared__ int   s_hist[2048];
    __shared__ float s_wred[32];
    __shared__ int   s_widx[32];
    __shared__ int   s_sel1, s_rank2, s_sel2, s_cntHi, s_cntSel;
    __shared__ float s_maxv, s_sumv;

    // ---- pass 1: zero fprobs row, histogram top 11 bits, row max ----
    for (int i = t; i < VOCAB; i += 1024) fp[i] = 0.0f;
    for (int i = t; i < 2048; i += 1024) s_hist[i] = 0;
    if (t == 0) { s_cntHi = 0; s_cntSel = 0; }
    __syncthreads();

    float mx = -__int_as_float(0x7f800000);
    for (int i4 = t; i4 < NF4; i4 += 1024) {
        float4 v = row4[i4];
        int gi = i4 * 4;
        float e[4] = {v.x, v.y, v.z, v.w};
#pragma unroll
        for (int j = 0; j < 4; j++) {
            if (gi + j < VOCAB) {
                mx = fmaxf(mx, e[j]);
                atomicAdd(&s_hist[fmap(e[j]) >> 21], 1);
            }
        }
    }
#pragma unroll
    for (int o = 16; o > 0; o >>= 1)
        mx = fmaxf(mx, __shfl_xor_sync(0xffffffffu, mx, o));
    if (lane == 0) s_wred[wid] = mx;
    __syncthreads();

    // warp 0: suffix-scan for sel1/rank2 ; warp 1: final max reduce
    if (wid == 0) {
        int acc = 0;
        for (int base = 2048 - 32; base >= 0; base -= 32) {
            int bin = base + 31 - lane;
            int c = s_hist[bin];
            int p = c;
            for (int o = 1; o < 32; o <<= 1) {
                int v = __shfl_up_sync(0xffffffffu, p, o);
                if (lane >= o) p += v;
            }
            int S = acc + p;
            unsigned msk = __ballot_sync(0xffffffffu, S >= RANK);
            if (msk) {
                int l = __ffs(msk) - 1;
                int Ssel = __shfl_sync(0xffffffffu, S, l);
                int csel = __shfl_sync(0xffffffffu, c, l);
                if (lane == 0) {
                    s_sel1  = base + 31 - l;
                    s_rank2 = RANK - (Ssel - csel);
                }
                break;
            }
            acc += __shfl_sync(0xffffffffu, p, 31);
        }
    } else if (wid == 1) {
        float m = s_wred[lane];
#pragma unroll
        for (int o = 16; o > 0; o >>= 1)
            m = fmaxf(m, __shfl_xor_sync(0xffffffffu, m, o));
        if (lane == 0) s_maxv = m;
    }
    __syncthreads();
    const int sel1 = s_sel1;
    const int rank2 = s_rank2;
    const float rmax = s_maxv;

    // zero hist for pass 2
    for (int i = t; i < 2048; i += 1024) s_hist[i] = 0;
    __syncthreads();

    // ---- pass 2: sum(exp(l-max)), collect hi keys, sel-bucket hist + stash ----
    float sum = 0.f;
    for (int i4 = t; i4 < NF4; i4 += 1024) {
        float4 v = row4[i4];
        int gi = i4 * 4;
        float e[4] = {v.x, v.y, v.z, v.w};
#pragma unroll
        for (int j = 0; j < 4; j++) {
            if (gi + j < VOCAB) {
                sum += expf(e[j] - rmax);
                unsigned k = fmap(e[j]);
                int top11 = (int)(k >> 21);
                if (top11 > sel1) {
                    int pos = atomicAdd(&s_cntHi, 1);   // bounded by RANK-rank2 <= 999
                    s_keys[pos] = ((unsigned long long)(~k) << 32) | (unsigned)(gi + j);
                } else if (top11 == sel1) {
                    atomicAdd(&s_hist[(k >> 10) & 0x7FF], 1);
                    int pos = atomicAdd(&s_cntSel, 1);
                    if (pos < NCAND)
                        s_sel[pos] = ((unsigned long long)(~k) << 32) | (unsigned)(gi + j);
                }
            }
        }
    }
#pragma unroll
    for (int o = 16; o > 0; o >>= 1)
        sum += __shfl_xor_sync(0xffffffffu, sum, o);
    if (lane == 0) s_wred[wid] = sum;
    __syncthreads();

    // warp 0: suffix-scan for sel2 ; warp 1: final sum reduce
    if (wid == 0) {
        int acc = 0;
        for (int base = 2048 - 32; base >= 0; base -= 32) {
            int bin = base + 31 - lane;
            int c = s_hist[bin];
            int p = c;
            for (int o = 1; o < 32; o <<= 1) {
                int v = __shfl_up_sync(0xffffffffu, p, o);
                if (lane >= o) p += v;
            }
            int S = acc + p;
            unsigned msk = __ballot_sync(0xffffffffu, S >= rank2);
            if (msk) {
                int l = __ffs(msk) - 1;
                if (lane == 0) s_sel2 = base + 31 - l;
                break;
            }
            acc += __shfl_sync(0xffffffffu, p, 31);
        }
    } else if (wid == 1) {
        float s = s_wred[lane];
#pragma unroll
        for (int o = 16; o > 0; o >>= 1)
            s += __shfl_xor_sync(0xffffffffu, s, o);
        if (lane == 0) s_sumv = s;
    }
    __syncthreads();
    const int sel2 = s_sel2;
    const float rsum = s_sumv;

    // ---- append sel-bucket keys with second-level bin >= sel2 ----
    int cntSel = s_cntSel; if (cntSel > NCAND) cntSel = NCAND;
    for (int i = t; i < cntSel; i += 1024) {
        unsigned long long key = s_sel[i];
        unsigned k = ~(unsigned)(key >> 32);
        if ((int)((k >> 10) & 0x7FF) >= sel2) {
            int pos = atomicAdd(&s_cntHi, 1);
            if (pos < NCAND) s_keys[pos] = key;
        }
    }
    __syncthreads();
    int cnt = s_cntHi; if (cnt > NCAND) cnt = NCAND;
    const int N = (cnt <= 1024) ? 1024 : NCAND;
    for (int i = t; i < N; i += 1024)
        if (i >= cnt) s_keys[i] = 0xFFFFFFFFFFFFFFFFull;
    __syncthreads();

    // ---- bitonic sort ascending (=> descending logit, stable ties) ----
    for (int k = 2; k <= N; k <<= 1) {
        for (int j = k >> 1; j > 0; j >>= 1) {
            for (int i = t; i < N; i += 1024) {
                int ixj = i ^ j;
                if (ixj > i) {
                    unsigned long long a = s_keys[i], c2 = s_keys[ixj];
                    bool asc = ((i & k) == 0);
                    if (asc ? (a > c2) : (a < c2)) {
                        s_keys[i] = c2;
                        s_keys[ixj] = a;
                    }
                }
            }
            __syncthreads();
        }
    }

    // ---- parallel top-p/top-k mask ----
    const int   K  = top_ks[b];
    const float tp = top_ps[b];
    const int limit = (cnt < K ? cnt : K);       // <= 999 < 1024

    float p = 0.f;
    int   idx = 0;
    const bool valid = (t < limit);
    if (valid) {
        unsigned long long key = s_keys[t];
        unsigned hi = (unsigned)(key >> 32);
        float logit = funmap(~hi);
        idx = (int)(unsigned)(key & 0xFFFFFFFFull);
        p = expf(logit - rmax) / rsum;
    }
    // block-wide exclusive scan of p
    float x = p;
    for (int o = 1; o < 32; o <<= 1) {
        float v = __shfl_up_sync(0xffffffffu, x, o);
        if (lane >= o) x += v;
    }
    if (lane == 31) s_wred[wid] = x;
    __syncthreads();
    if (wid == 0) {
        float w = s_wred[lane];
        float y = w;
        for (int o = 1; o < 32; o <<= 1) {
            float v = __shfl_up_sync(0xffffffffu, y, o);
            if (lane >= o) y += v;
        }
        s_wred[lane] = y - w;
    }
    __syncthreads();
    float excl = s_wred[wid] + x - p;
    const bool survive = valid && (excl <= tp);

    // ---- scatter fprobs + gumbel argmax over survivors ----
    float best  = -__int_as_float(0x7f800000);
    int   bestv = 0x7fffffff;
    if (survive) {
        fp[idx] = p;
        float g = jax_gumbel((unsigned)(b * VOCAB + idx));
        best  = logf(p) + g;
        bestv = idx;
    }
    // warp reduce argmax (tie: smaller idx)
#pragma unroll
    for (int o = 16; o > 0; o >>= 1) {
        float ob = __shfl_xor_sync(0xffffffffu, best, o);
        int   ov = __shfl_xor_sync(0xffffffffu, bestv, o);
        if (ob > best || (ob == best && ov < bestv)) { best = ob; bestv = ov; }
    }
    if (lane == 0) { s_wred[wid] = best; s_widx[wid] = bestv; }
    __syncthreads();
    if (wid == 0) {
        best  = s_wred[lane];
        bestv = s_widx[lane];
#pragma unroll
        for (int o = 16; o > 0; o >>= 1) {
            float ob = __shfl_xor_sync(0xffffffffu, best, o);
            int   ov = __shfl_xor_sync(0xffffffffu, bestv, o);
            if (ob > best || (ob == best && ov < bestv)) { best = ob; bestv = ov; }
        }
        if (lane == 0) {
            out_ids[b] = (float)bestv;
            out_lp[b]  = row[bestv] - rmax - logf(rsum);
        }
    }
}

// =========================================================================
// launch
// =========================================================================
extern "C" void kernel_launch(void* const* d_in, const int* in_sizes, int n_in,
                              void* d_out, int out_size) {
    const float* H     = (const float*)d_in[0];
    const float* E     = (const float*)d_in[1];
    const float* temps = (const float*)d_in[2];
    const float* tps   = (const float*)d_in[3];
    const int*   tks   = (const int*)d_in[4];

    float* out = (float*)d_out;
    int fbase = out_size - BATCH * VOCAB;
    if (fbase < 0) fbase = 0;
    float* out_ids = out;
    float* out_lp  = out + ((fbase >= 2 * BATCH) ? BATCH : 0);
    float* out_fp  = out + fbase;

    cudaFuncSetAttribute(gemm_hmma_kernel,
                         cudaFuncAttributeMaxDynamicSharedMemorySize, GSMEM);

    gemm_hmma_kernel<<<(VOCAB + TN - 1) / TN, 256, GSMEM>>>(H, E, temps);
    sample_kernel<<<BATCH, 1024>>>(tps, tks, out_ids, out_lp, out_fp);
}

// round 10
// speedup vs baseline: 3.2035x; 1.0009x over previous
#include <cuda_runtime.h>
#include <cuda_bf16.h>
#include <cstdint>

#define BATCH 64
#define VOCAB 50257
#define VP    50304          /* padded logits row stride (393*128) */
#define DIM   1024

// ---------------- scratch (static __device__, no allocs) ----------------
__device__ float g_logits[(size_t)BATCH * VP];
__device__ float g_sums[BATCH];          // Sum_n exp(logit) per row; zeroed by sample_kernel

// =========================================================================
// Kernel 1: HMMA bf16-split GEMM, double-buffered smem
//   logits[m,n] = (H[m,:] . E[n,:]) / temp[m]
//   acc = Ahi*Bhi + Alo*Bhi + Ahi*Blo   (Alo*Blo ~2^-18, dropped)
//   epilogue also accumulates Z_m = Sum_n exp(logits[m,n]) into g_sums
// =========================================================================
#define TN   128
#define BK   32
#define NC   (DIM / BK)      /* 32 chunks */
#define SAST 40              /* smem row stride in bf16 elems (80B) */
#define ABUF (128 * SAST)
#define BBUF (256 * SAST)
#define BUFU16 (ABUF + BBUF)
#define GSMEM (2 * BUFU16 * 2)  /* 61440 B dynamic */

__device__ __forceinline__ uint32_t smem_u32(const void* p) {
    uint32_t a;
    asm("{ .reg .u64 t; cvta.to.shared.u64 t, %1; cvt.u32.u64 %0, t; }" : "=r"(a) : "l"(p));
    return a;
}

#define LDMX4(d, addr)                                                            \
    asm volatile("ldmatrix.sync.aligned.m8n8.x4.shared.b16 {%0,%1,%2,%3}, [%4];"  \
        : "=r"((d)[0]), "=r"((d)[1]), "=r"((d)[2]), "=r"((d)[3]) : "r"(addr))

#define MMA16816(c, a, b0, b1)                                                    \
    asm volatile("mma.sync.aligned.m16n8k16.row.col.f32.bf16.bf16.f32 "           \
        "{%0,%1,%2,%3}, {%4,%5,%6,%7}, {%8,%9}, {%0,%1,%2,%3};"                   \
        : "+f"((c)[0]), "+f"((c)[1]), "+f"((c)[2]), "+f"((c)[3])                  \
        : "r"((a)[0]), "r"((a)[1]), "r"((a)[2]), "r"((a)[3]), "r"(b0), "r"(b1))

__device__ __forceinline__ void split4(float4 v, uint2& hi, uint2& lo) {
    __nv_bfloat16 h0 = __float2bfloat16(v.x), h1 = __float2bfloat16(v.y);
    __nv_bfloat16 h2 = __float2bfloat16(v.z), h3 = __float2bfloat16(v.w);
    __nv_bfloat16 l0 = __float2bfloat16(v.x - __bfloat162float(h0));
    __nv_bfloat16 l1 = __float2bfloat16(v.y - __bfloat162float(h1));
    __nv_bfloat16 l2 = __float2bfloat16(v.z - __bfloat162float(h2));
    __nv_bfloat16 l3 = __float2bfloat16(v.w - __bfloat162float(h3));
    hi.x = ((uint32_t)__bfloat16_as_ushort(h1) << 16) | __bfloat16_as_ushort(h0);
    hi.y = ((uint32_t)__bfloat16_as_ushort(h3) << 16) | __bfloat16_as_ushort(h2);
    lo.x = ((uint32_t)__bfloat16_as_ushort(l1) << 16) | __bfloat16_as_ushort(l0);
    lo.y = ((uint32_t)__bfloat16_as_ushort(l3) << 16) | __bfloat16_as_ushort(l2);
}

__global__ __launch_bounds__(256) void gemm_hmma_kernel(
    const float* __restrict__ H,
    const float* __restrict__ E,
    const float* __restrict__ temps)
{
    extern __shared__ __align__(16) uint16_t dynsm[];

    const int t    = threadIdx.x;
    const int lane = t & 31;
    const int wid  = t >> 5;
    const int n0   = blockIdx.x * TN;
    const int wm   = (wid >> 2) * 32;
    const int wn   = (wid & 3) * 32;

    float acc[2][4][4];
#pragma unroll
    for (int i = 0; i < 2; i++)
#pragma unroll
        for (int j = 0; j < 4; j++)
#pragma unroll
            for (int k = 0; k < 4; k++) acc[i][j][k] = 0.0f;

    float4 ra[2], rb[4];

    auto loadG = [&](int c) {
        const int k0 = c * BK;
#pragma unroll
        for (int i = 0; i < 2; i++) {
            int idx = t + i * 256;
            int r = idx >> 3, c4 = idx & 7;
            ra[i] = __ldg(reinterpret_cast<const float4*>(H + r * DIM + k0 + c4 * 4));
        }
#pragma unroll
        for (int i = 0; i < 4; i++) {
            int idx = t + i * 256;
            int r = idx >> 3, c4 = idx & 7;
            int gn = n0 + r;
            rb[i] = (gn < VOCAB)
                ? __ldg(reinterpret_cast<const float4*>(E + (size_t)gn * DIM + k0 + c4 * 4))
                : make_float4(0.f, 0.f, 0.f, 0.f);
        }
    };
    auto storeS = [&](int buf) {
        uint16_t* sA = dynsm + buf * BUFU16;
        uint16_t* sB = sA + ABUF;
#pragma unroll
        for (int i = 0; i < 2; i++) {
            int idx = t + i * 256;
            int r = idx >> 3, c4 = idx & 7;
            uint2 hi, lo;
            split4(ra[i], hi, lo);
            *reinterpret_cast<uint2*>(&sA[r * SAST + c4 * 4]) = hi;
            *reinterpret_cast<uint2*>(&sA[(r + 64) * SAST + c4 * 4]) = lo;
        }
#pragma unroll
        for (int i = 0; i < 4; i++) {
            int idx = t + i * 256;
            int r = idx >> 3, c4 = idx & 7;
            uint2 hi, lo;
            split4(rb[i], hi, lo);
            *reinterpret_cast<uint2*>(&sB[r * SAST + c4 * 4]) = hi;
            *reinterpret_cast<uint2*>(&sB[(r + 128) * SAST + c4 * 4]) = lo;
        }
    };

    const uint32_t dynBase = smem_u32(dynsm);
    const int rsel = (lane & 7) + ((lane >> 3) & 1) * 8;
    const int csel = (lane >> 4) * 8;

    loadG(0);
    storeS(0);
    __syncthreads();

    for (int c = 0; c < NC; c++) {
        if (c + 1 < NC) loadG(c + 1);

        const uint32_t aBase = dynBase + (uint32_t)(c & 1) * (BUFU16 * 2);
        const uint32_t bBase = aBase + ABUF * 2;
#pragma unroll
        for (int ks = 0; ks < 2; ks++) {
            uint32_t af[2][2][4];
#pragma unroll
            for (int fm = 0; fm < 2; fm++)
#pragma unroll
                for (int h = 0; h < 2; h++) {
                    uint32_t addr = aBase +
                        (uint32_t)(((h * 64 + wm + fm * 16 + rsel) * SAST) + ks * 16 + csel) * 2;
                    LDMX4(af[fm][h], addr);
                }
            uint32_t bf[2][2][4];
#pragma unroll
            for (int np = 0; np < 2; np++)
#pragma unroll
                for (int h = 0; h < 2; h++) {
                    uint32_t addr = bBase +
                        (uint32_t)(((h * 128 + wn + np * 16 + rsel) * SAST) + ks * 16 + csel) * 2;
                    LDMX4(bf[np][h], addr);
                }
#pragma unroll
            for (int fm = 0; fm < 2; fm++)
#pragma unroll
                for (int fn = 0; fn < 4; fn++) {
                    int np = fn >> 1, sb = fn & 1;
                    MMA16816(acc[fm][fn], af[fm][0], bf[np][0][sb], bf[np][0][sb + 2]); // hi*hi
                    MMA16816(acc[fm][fn], af[fm][1], bf[np][0][sb], bf[np][0][sb + 2]); // lo*hi
                    MMA16816(acc[fm][fn], af[fm][0], bf[np][1][sb], bf[np][1][sb + 2]); // hi*lo
                }
        }
        if (c + 1 < NC) storeS((c + 1) & 1);
        __syncthreads();
    }

    // ---- epilogue: /temp, store logits, accumulate exp-sums ----
    const bool tileFull = true;  // stores use padded VP stride; cols beyond VOCAB land in pad
#pragma unroll
    for (int fm = 0; fm < 2; fm++) {
        int m = wm + fm * 16 + (lane >> 2);
        float t0 = __ldg(temps + m);
        float t1 = __ldg(temps + m + 8);
        float s0 = 0.f, s1 = 0.f;
#pragma unroll
        for (int fn = 0; fn < 4; fn++) {
            int n = n0 + wn + fn * 8 + (lane & 3) * 2;
            float2 v0 = make_float2(acc[fm][fn][0] / t0, acc[fm][fn][1] / t0);
            float2 v1 = make_float2(acc[fm][fn][2] / t1, acc[fm][fn][3] / t1);
            *reinterpret_cast<float2*>(&g_logits[(size_t)m * VP + n]) = v0;
            *reinterpret_cast<float2*>(&g_logits[(size_t)(m + 8) * VP + n]) = v1;
            // exp-sum, guarding the final partial tile (n beyond VOCAB excluded)
            if (n < VOCAB)     s0 += expf(v0.x);
            if (n + 1 < VOCAB) s0 += expf(v0.y);
            if (n < VOCAB)     s1 += expf(v1.x);
            if (n + 1 < VOCAB) s1 += expf(v1.y);
        }
        // reduce across the 4 quad lanes (lane&3) holding the same rows
        s0 += __shfl_xor_sync(0xffffffffu, s0, 1);
        s0 += __shfl_xor_sync(0xffffffffu, s0, 2);
        s1 += __shfl_xor_sync(0xffffffffu, s1, 1);
        s1 += __shfl_xor_sync(0xffffffffu, s1, 2);
        if ((lane & 3) == 0) {
            atomicAdd(&g_sums[m], s0);
            atomicAdd(&g_sums[m + 8], s1);
        }
    }
    (void)tileFull;
}

// =========================================================================
// Kernel 2: fused top-k select + top-p/top-k + JAX sample (no exp pass)
// =========================================================================
__device__ __forceinline__ unsigned fmap(float f) {
    unsigned u = __float_as_uint(f);
    return (u & 0x80000000u) ? ~u : (u | 0x80000000u);
}
__device__ __forceinline__ float funmap(unsigned u) {
    unsigned b = (u & 0x80000000u) ? (u & 0x7fffffffu) : ~u;
    return __uint_as_float(b);
}
__device__ __forceinline__ unsigned rotl32(unsigned x, int r) {
    return (x << r) | (x >> (32 - r));
}
// jax threefry2x32, key = (0, 42)
__device__ __forceinline__ uint2 threefry_0_42(unsigned c0, unsigned c1) {
    const unsigned ks0 = 0u, ks1 = 42u;
    const unsigned ks2 = ks0 ^ ks1 ^ 0x1BD11BDAu;
    unsigned x0 = c0 + ks0;
    unsigned x1 = c1 + ks1;
#define TF_ROUND(r) { x0 += x1; x1 = rotl32(x1, r); x1 ^= x0; }
    TF_ROUND(13) TF_ROUND(15) TF_ROUND(26) TF_ROUND(6)
    x0 += ks1; x1 += ks2 + 1u;
    TF_ROUND(17) TF_ROUND(29) TF_ROUND(16) TF_ROUND(24)
    x0 += ks2; x1 += ks0 + 2u;
    TF_ROUND(13) TF_ROUND(15) TF_ROUND(26) TF_ROUND(6)
    x0 += ks0; x1 += ks1 + 3u;
    TF_ROUND(17) TF_ROUND(29) TF_ROUND(16) TF_ROUND(24)
    x0 += ks1; x1 += ks2 + 4u;
    TF_ROUND(13) TF_ROUND(15) TF_ROUND(26) TF_ROUND(6)
    x0 += ks2; x1 += ks0 + 5u;
#undef TF_ROUND
    return make_uint2(x0, x1);
}
// partitionable threefry layout: bits = b1 ^ b2 of threefry(key, (0, i))
__device__ __forceinline__ float jax_gumbel(unsigned i) {
    uint2 r = threefry_0_42(0u, i);
    unsigned bits = r.x ^ r.y;
    float f = __uint_as_float((bits >> 9) | 0x3f800000u) - 1.0f;
    float u = (f == 0.0f) ? 1.17549435e-38f : f;
    return -logf(-logf(u));
}

#define NCAND 2048
#define RANK  1000
#define NF4   12565          /* ceil(VOCAB/4); reads stay inside VP padding */

__global__ __launch_bounds__(1024) void sample_kernel(
    const float* __restrict__ top_ps,
    const int*   __restrict__ top_ks,
    float* __restrict__ out_ids,
    float* __restrict__ out_lp,
    float* __restrict__ out_fprobs)
{
    const int b    = blockIdx.x;
    const int t    = threadIdx.x;
    const int lane = t & 31;
    const int wid  = t >> 5;
    const float* row = g_logits + (size_t)b * VP;
    const float4* row4 = reinterpret_cast<const float4*>(row);
    float* fp = out_fprobs + (size_t)b * VOCAB;

    const float logZ = logf(g_sums[b]);

    __shared__ unsigned long long s_keys[NCAND];
    __shared__ unsigned long long s_sel[NCAND];
    __shared__ int   s_hist[2048];
    __shared__ float s_wred[32];
    __shared__ int   s_widx[32];
    __shared__ int   s_sel1, s_rank2, s_sel2, s_cntHi, s_cntSel;

    // ---- pass 1: zero fprobs row + histogram of top 11 bits ----
    for (int i = t; i < VOCAB; i += 1024) fp[i] = 0.0f;
    for (int i = t; i < 2048; i += 1024) s_hist[i] = 0;
    if (t == 0) { s_cntHi = 0; s_cntSel = 0; }
    __syncthreads();

    for (int i4 = t; i4 < NF4; i4 += 1024) {
        float4 v = row4[i4];
        int gi = i4 * 4;
        float e[4] = {v.x, v.y, v.z, v.w};
#pragma unroll
        for (int j = 0; j < 4; j++)
            if (gi + j < VOCAB)
                atomicAdd(&s_hist[fmap(e[j]) >> 21], 1);
    }
    __syncthreads();

    // warp 0: suffix-scan for sel1/rank2
    if (wid == 0) {
        int acc = 0;
        for (int base = 2048 - 32; base >= 0; base -= 32) {
            int bin = base + 31 - lane;
            int c = s_hist[bin];
            int p = c;
            for (int o = 1; o < 32; o <<= 1) {
                int v = __shfl_up_sync(0xffffffffu, p, o);
                if (lane >= o) p += v;
            }
            int S = acc + p;
            unsigned msk = __ballot_sync(0xffffffffu, S >= RANK);
            if (msk) {
                int l = __ffs(msk) - 1;
                int Ssel = __shfl_sync(0xffffffffu, S, l);
                int csel = __shfl_sync(0xffffffffu, c, l);
                if (lane == 0) {
                    s_sel1  = base + 31 - l;
                    s_rank2 = RANK - (Ssel - csel);
                }
                break;
            }
            acc += __shfl_sync(0xffffffffu, p, 31);
        }
    }
    __syncthreads();
    const int sel1 = s_sel1;
    const int rank2 = s_rank2;

    for (int i = t; i < 2048; i += 1024) s_hist[i] = 0;
    __syncthreads();

    // ---- pass 2: collect hi keys, sel-bucket hist + stash ----
    for (int i4 = t; i4 < NF4; i4 += 1024) {
        float4 v = row4[i4];
        int gi = i4 * 4;
        float e[4] = {v.x, v.y, v.z, v.w};
#pragma unroll
        for (int j = 0; j < 4; j++) {
            if (gi + j < VOCAB) {
                unsigned k = fmap(e[j]);
                int top11 = (int)(k >> 21);
                if (top11 > sel1) {
                    int pos = atomicAdd(&s_cntHi, 1);   // bounded by RANK-1
                    s_keys[pos] = ((unsigned long long)(~k) << 32) | (unsigned)(gi + j);
                } else if (top11 == sel1) {
                    atomicAdd(&s_hist[(k >> 10) & 0x7FF], 1);
                    int pos = atomicAdd(&s_cntSel, 1);
                    if (pos < NCAND)
                        s_sel[pos] = ((unsigned long long)(~k) << 32) | (unsigned)(gi + j);
                }
            }
        }
    }
    __syncthreads();

    // warp 0: suffix-scan for sel2
    if (wid == 0) {
        int acc = 0;
        for (int base = 2048 - 32; base >= 0; base -= 32) {
            int bin = base + 31 - lane;
            int c = s_hist[bin];
            int p = c;
            for (int o = 1; o < 32; o <<= 1) {
                int v = __shfl_up_sync(0xffffffffu, p, o);
                if (lane >= o) p += v;
            }
            int S = acc + p;
            unsigned msk = __ballot_sync(0xffffffffu, S >= rank2);
            if (msk) {
                int l = __ffs(msk) - 1;
                if (lane == 0) s_sel2 = base + 31 - l;
                break;
            }
            acc += __shfl_sync(0xffffffffu, p, 31);
        }
    }
    __syncthreads();
    const int sel2 = s_sel2;

    // ---- append sel-bucket keys with second-level bin >= sel2 ----
    int cntSel = s_cntSel; if (cntSel > NCAND) cntSel = NCAND;
    for (int i = t; i < cntSel; i += 1024) {
        unsigned long long key = s_sel[i];
        unsigned k = ~(unsigned)(key >> 32);
        if ((int)((k >> 10) & 0x7FF) >= sel2) {
            int pos = atomicAdd(&s_cntHi, 1);
            if (pos < NCAND) s_keys[pos] = key;
        }
    }
    __syncthreads();
    int cnt = s_cntHi; if (cnt > NCAND) cnt = NCAND;
    const int N = (cnt <= 1024) ? 1024 : NCAND;
    for (int i = t; i < N; i += 1024)
        if (i >= cnt) s_keys[i] = 0xFFFFFFFFFFFFFFFFull;
    __syncthreads();

    // ---- bitonic sort ascending (=> descending logit, stable ties) ----
    for (int k = 2; k <= N; k <<= 1) {
        for (int j = k >> 1; j > 0; j >>= 1) {
            for (int i = t; i < N; i += 1024) {
                int ixj = i ^ j;
                if (ixj > i) {
                    unsigned long long a = s_keys[i], c2 = s_keys[ixj];
                    bool asc = ((i & k) == 0);
                    if (asc ? (a > c2) : (a < c2)) {
                        s_keys[i] = c2;
                        s_keys[ixj] = a;
                    }
                }
            }
            __syncthreads();
        }
    }

    // ---- parallel top-p/top-k mask ----
    const int   K  = top_ks[b];
    const float tp = top_ps[b];
    const int limit = (cnt < K ? cnt : K);       // <= 999 < 1024

    float p = 0.f;
    int   idx = 0;
    const bool valid = (t < limit);
    if (valid) {
        unsigned long long key = s_keys[t];
        unsigned hi = (unsigned)(key >> 32);
        float logit = funmap(~hi);
        idx = (int)(unsigned)(key & 0xFFFFFFFFull);
        p = expf(logit - logZ);
    }
    // block-wide exclusive scan of p
    float x = p;
    for (int o = 1; o < 32; o <<= 1) {
        float v = __shfl_up_sync(0xffffffffu, x, o);
        if (lane >= o) x += v;
    }
    if (lane == 31) s_wred[wid] = x;
    __syncthreads();
    if (wid == 0) {
        float w = s_wred[lane];
        float y = w;
        for (int o = 1; o < 32; o <<= 1) {
            float v = __shfl_up_sync(0xffffffffu, y, o);
            if (lane >= o) y += v;
        }
        s_wred[lane] = y - w;
    }
    __syncthreads();
    float excl = s_wred[wid] + x - p;
    const bool survive = valid && (excl <= tp);

    // ---- scatter fprobs + gumbel argmax over survivors ----
    float best  = -__int_as_float(0x7f800000);
    int   bestv = 0x7fffffff;
    if (survive) {
        fp[idx] = p;
        float g = jax_gumbel((unsigned)(b * VOCAB + idx));
        best  = logf(p) + g;
        bestv = idx;
    }
#pragma unroll
    for (int o = 16; o > 0; o >>= 1) {
        float ob = __shfl_xor_sync(0xffffffffu, best, o);
        int   ov = __shfl_xor_sync(0xffffffffu, bestv, o);
        if (ob > best || (ob == best && ov < bestv)) { best = ob; bestv = ov; }
    }
    if (lane == 0) { s_wred[wid] = best; s_widx[wid] = bestv; }
    __syncthreads();
    if (wid == 0) {
        best  = s_wred[lane];
        bestv = s_widx[lane];
#pragma unroll
        for (int o = 16; o > 0; o >>= 1) {
            float ob = __shfl_xor_sync(0xffffffffu, best, o);
            int   ov = __shfl_xor_sync(0xffffffffu, bestv, o);
            if (ob > best || (ob == best && ov < bestv)) { best = ob; bestv = ov; }
        }
        if (lane == 0) {
            out_ids[b] = (float)bestv;
            out_lp[b]  = row[bestv] - logZ;
            g_sums[b]  = 0.0f;   // reset for next graph replay
        }
    }
}

// =========================================================================
// launch
// =========================================================================
extern "C" void kernel_launch(void* const* d_in, const int* in_sizes, int n_in,
                              void* d_out, int out_size) {
    const float* H     = (const float*)d_in[0];
    const float* E     = (const float*)d_in[1];
    const float* temps = (const float*)d_in[2];
    const float* tps   = (const float*)d_in[3];
    const int*   tks   = (const int*)d_in[4];

    float* out = (float*)d_out;
    int fbase = out_size - BATCH * VOCAB;
    if (fbase < 0) fbase = 0;
    float* out_ids = out;
    float* out_lp  = out + ((fbase >= 2 * BATCH) ? BATCH : 0);
    float* out_fp  = out + fbase;

    cudaFuncSetAttribute(gemm_hmma_kernel,
                         cudaFuncAttributeMaxDynamicSharedMemorySize, GSMEM);

    gemm_hmma_kernel<<<(VOCAB + TN - 1) / TN, 256, GSMEM>>>(H, E, temps);
    sample_kernel<<<BATCH, 1024>>>(tps, tks, out_ids, out_lp, out_fp);
}

// round 11
// speedup vs baseline: 3.2398x; 1.0113x over previous
#include <cuda_runtime.h>
#include <cuda_bf16.h>
#include <cstdint>

#define BATCH 64
#define VOCAB 50257
#define VP    50304          /* padded logits row stride (393*128) */
#define DIM   1024
#define NEGINF __int_as_float(0xff800000)

// ---------------- scratch (static __device__, no allocs) ----------------
__device__ float g_logits[(size_t)BATCH * VP];
__device__ float g_sums[BATCH];              // Sum exp(logit); zeroed by sample_kernel
__device__ int   g_hist[BATCH * 2048];       // per-row top-11-bit hist; zeroed by sample_kernel

// =========================================================================
// Kernel 1: HMMA bf16-split GEMM, double-buffered smem, 2 CTA/SM
// =========================================================================
#define TN   128
#define BK   32
#define NC   (DIM / BK)
#define SAST 40
#define ABUF (128 * SAST)
#define BBUF (256 * SAST)
#define BUFU16 (ABUF + BBUF)
#define GSMEM (2 * BUFU16 * 2)  /* 61440 B dynamic */

__device__ __forceinline__ uint32_t smem_u32(const void* p) {
    uint32_t a;
    asm("{ .reg .u64 t; cvta.to.shared.u64 t, %1; cvt.u32.u64 %0, t; }" : "=r"(a) : "l"(p));
    return a;
}

#define LDMX4(d, addr)                                                            \
    asm volatile("ldmatrix.sync.aligned.m8n8.x4.shared.b16 {%0,%1,%2,%3}, [%4];"  \
        : "=r"((d)[0]), "=r"((d)[1]), "=r"((d)[2]), "=r"((d)[3]) : "r"(addr))

#define MMA16816(c, a, b0, b1)                                                    \
    asm volatile("mma.sync.aligned.m16n8k16.row.col.f32.bf16.bf16.f32 "           \
        "{%0,%1,%2,%3}, {%4,%5,%6,%7}, {%8,%9}, {%0,%1,%2,%3};"                   \
        : "+f"((c)[0]), "+f"((c)[1]), "+f"((c)[2]), "+f"((c)[3])                  \
        : "r"((a)[0]), "r"((a)[1]), "r"((a)[2]), "r"((a)[3]), "r"(b0), "r"(b1))

__device__ __forceinline__ void split4(float4 v, uint2& hi, uint2& lo) {
    __nv_bfloat16 h0 = __float2bfloat16(v.x), h1 = __float2bfloat16(v.y);
    __nv_bfloat16 h2 = __float2bfloat16(v.z), h3 = __float2bfloat16(v.w);
    __nv_bfloat16 l0 = __float2bfloat16(v.x - __bfloat162float(h0));
    __nv_bfloat16 l1 = __float2bfloat16(v.y - __bfloat162float(h1));
    __nv_bfloat16 l2 = __float2bfloat16(v.z - __bfloat162float(h2));
    __nv_bfloat16 l3 = __float2bfloat16(v.w - __bfloat162float(h3));
    hi.x = ((uint32_t)__bfloat16_as_ushort(h1) << 16) | __bfloat16_as_ushort(h0);
    hi.y = ((uint32_t)__bfloat16_as_ushort(h3) << 16) | __bfloat16_as_ushort(h2);
    lo.x = ((uint32_t)__bfloat16_as_ushort(l1) << 16) | __bfloat16_as_ushort(l0);
    lo.y = ((uint32_t)__bfloat16_as_ushort(l3) << 16) | __bfloat16_as_ushort(l2);
}

__global__ __launch_bounds__(256, 2) void gemm_hmma_kernel(
    const float* __restrict__ H,
    const float* __restrict__ E,
    const float* __restrict__ temps)
{
    extern __shared__ __align__(16) uint16_t dynsm[];

    const int t    = threadIdx.x;
    const int lane = t & 31;
    const int wid  = t >> 5;
    const int n0   = blockIdx.x * TN;
    const int wm   = (wid >> 2) * 32;
    const int wn   = (wid & 3) * 32;

    float acc[2][4][4];
#pragma unroll
    for (int i = 0; i < 2; i++)
#pragma unroll
        for (int j = 0; j < 4; j++)
#pragma unroll
            for (int k = 0; k < 4; k++) acc[i][j][k] = 0.0f;

    float4 ra[2], rb[4];

    auto loadG = [&](int c) {
        const int k0 = c * BK;
#pragma unroll
        for (int i = 0; i < 2; i++) {
            int idx = t + i * 256;
            int r = idx >> 3, c4 = idx & 7;
            ra[i] = __ldg(reinterpret_cast<const float4*>(H + r * DIM + k0 + c4 * 4));
        }
#pragma unroll
        for (int i = 0; i < 4; i++) {
            int idx = t + i * 256;
            int r = idx >> 3, c4 = idx & 7;
            int gn = n0 + r;
            rb[i] = (gn < VOCAB)
                ? __ldg(reinterpret_cast<const float4*>(E + (size_t)gn * DIM + k0 + c4 * 4))
                : make_float4(0.f, 0.f, 0.f, 0.f);
        }
    };
    auto storeS = [&](int buf) {
        uint16_t* sA = dynsm + buf * BUFU16;
        uint16_t* sB = sA + ABUF;
#pragma unroll
        for (int i = 0; i < 2; i++) {
            int idx = t + i * 256;
            int r = idx >> 3, c4 = idx & 7;
            uint2 hi, lo;
            split4(ra[i], hi, lo);
            *reinterpret_cast<uint2*>(&sA[r * SAST + c4 * 4]) = hi;
            *reinterpret_cast<uint2*>(&sA[(r + 64) * SAST + c4 * 4]) = lo;
        }
#pragma unroll
        for (int i = 0; i < 4; i++) {
            int idx = t + i * 256;
            int r = idx >> 3, c4 = idx & 7;
            uint2 hi, lo;
            split4(rb[i], hi, lo);
            *reinterpret_cast<uint2*>(&sB[r * SAST + c4 * 4]) = hi;
            *reinterpret_cast<uint2*>(&sB[(r + 128) * SAST + c4 * 4]) = lo;
        }
    };

    const uint32_t dynBase = smem_u32(dynsm);
    const int rsel = (lane & 7) + ((lane >> 3) & 1) * 8;
    const int csel = (lane >> 4) * 8;

    loadG(0);
    storeS(0);
    __syncthreads();

    for (int c = 0; c < NC; c++) {
        if (c + 1 < NC) loadG(c + 1);

        const uint32_t aBase = dynBase + (uint32_t)(c & 1) * (BUFU16 * 2);
        const uint32_t bBase = aBase + ABUF * 2;
#pragma unroll
        for (int ks = 0; ks < 2; ks++) {
            uint32_t af[2][2][4];
#pragma unroll
            for (int fm = 0; fm < 2; fm++)
#pragma unroll
                for (int h = 0; h < 2; h++) {
                    uint32_t addr = aBase +
                        (uint32_t)(((h * 64 + wm + fm * 16 + rsel) * SAST) + ks * 16 + csel) * 2;
                    LDMX4(af[fm][h], addr);
                }
            uint32_t bf[2][2][4];
#pragma unroll
            for (int np = 0; np < 2; np++)
#pragma unroll
                for (int h = 0; h < 2; h++) {
                    uint32_t addr = bBase +
                        (uint32_t)(((h * 128 + wn + np * 16 + rsel) * SAST) + ks * 16 + csel) * 2;
                    LDMX4(bf[np][h], addr);
                }
#pragma unroll
            for (int fm = 0; fm < 2; fm++)
#pragma unroll
                for (int fn = 0; fn < 4; fn++) {
                    int np = fn >> 1, sb = fn & 1;
                    MMA16816(acc[fm][fn], af[fm][0], bf[np][0][sb], bf[np][0][sb + 2]); // hi*hi
                    MMA16816(acc[fm][fn], af[fm][1], bf[np][0][sb], bf[np][0][sb + 2]); // lo*hi
                    MMA16816(acc[fm][fn], af[fm][0], bf[np][1][sb], bf[np][1][sb + 2]); // hi*lo
                }
        }
        if (c + 1 < NC) storeS((c + 1) & 1);
        __syncthreads();
    }

    // ---- epilogue: /temp, pad-poison with -inf, store, exp-sum ----
#pragma unroll
    for (int fm = 0; fm < 2; fm++) {
        int m = wm + fm * 16 + (lane >> 2);
        float t0 = __ldg(temps + m);
        float t1 = __ldg(temps + m + 8);
        float s0 = 0.f, s1 = 0.f;
#pragma unroll
        for (int fn = 0; fn < 4; fn++) {
            int n = n0 + wn + fn * 8 + (lane & 3) * 2;
            bool v0ok = (n < VOCAB), v1ok = (n + 1 < VOCAB);
            float2 v0 = make_float2(v0ok ? acc[fm][fn][0] / t0 : NEGINF,
                                    v1ok ? acc[fm][fn][1] / t0 : NEGINF);
            float2 v1 = make_float2(v0ok ? acc[fm][fn][2] / t1 : NEGINF,
                                    v1ok ? acc[fm][fn][3] / t1 : NEGINF);
            *reinterpret_cast<float2*>(&g_logits[(size_t)m * VP + n]) = v0;
            *reinterpret_cast<float2*>(&g_logits[(size_t)(m + 8) * VP + n]) = v1;
            if (v0ok) { s0 += expf(v0.x); s1 += expf(v1.x); }
            if (v1ok) { s0 += expf(v0.y); s1 += expf(v1.y); }
        }
        s0 += __shfl_xor_sync(0xffffffffu, s0, 1);
        s0 += __shfl_xor_sync(0xffffffffu, s0, 2);
        s1 += __shfl_xor_sync(0xffffffffu, s1, 1);
        s1 += __shfl_xor_sync(0xffffffffu, s1, 2);
        if ((lane & 3) == 0) {
            atomicAdd(&g_sums[m], s0);
            atomicAdd(&g_sums[m + 8], s1);
        }
    }
}

// =========================================================================
// key mapping helpers
// =========================================================================
__device__ __forceinline__ unsigned fmap(float f) {
    unsigned u = __float_as_uint(f);
    return (u & 0x80000000u) ? ~u : (u | 0x80000000u);
}
__device__ __forceinline__ float funmap(unsigned u) {
    unsigned b = (u & 0x80000000u) ? (u & 0x7fffffffu) : ~u;
    return __uint_as_float(b);
}

// =========================================================================
// Kernel 2: sliced histogram + fprobs zeroing (grid: 4 slices x 64 rows)
// =========================================================================
#define NSLICE   4
#define SLICE_F4 (VP / 4 / NSLICE)     /* 3144 float4 per slice */
#define SLICE_EL (VP / NSLICE)         /* 12576 floats */

__global__ __launch_bounds__(1024) void hist_kernel(float* __restrict__ out_fprobs)
{
    const int s = blockIdx.x;
    const int b = blockIdx.y;
    const int t = threadIdx.x;

    __shared__ int s_hist[2048];
    for (int i = t; i < 2048; i += 1024) s_hist[i] = 0;

    // zero this slice of the fprobs row
    {
        float* fp = out_fprobs + (size_t)b * VOCAB;
        int lo = s * SLICE_EL;
        int hi = lo + SLICE_EL; if (hi > VOCAB) hi = VOCAB;
        for (int i = lo + t; i < hi; i += 1024) fp[i] = 0.0f;
    }
    __syncthreads();

    const float4* row4 = reinterpret_cast<const float4*>(g_logits + (size_t)b * VP);
    const int base = s * SLICE_F4;
    for (int i4 = t; i4 < SLICE_F4; i4 += 1024) {
        float4 v = row4[base + i4];
        atomicAdd(&s_hist[fmap(v.x) >> 21], 1);
        atomicAdd(&s_hist[fmap(v.y) >> 21], 1);
        atomicAdd(&s_hist[fmap(v.z) >> 21], 1);
        atomicAdd(&s_hist[fmap(v.w) >> 21], 1);
    }
    __syncthreads();

    int* gh = g_hist + b * 2048;
    for (int i = t; i < 2048; i += 1024) {
        int v = s_hist[i];
        if (v) atomicAdd(&gh[i], v);
    }
}

// =========================================================================
// Kernel 3: selection + single collect pass + top-p/top-k + JAX sample
// =========================================================================
__device__ __forceinline__ unsigned rotl32(unsigned x, int r) {
    return (x << r) | (x >> (32 - r));
}
__device__ __forceinline__ uint2 threefry_0_42(unsigned c0, unsigned c1) {
    const unsigned ks0 = 0u, ks1 = 42u;
    const unsigned ks2 = ks0 ^ ks1 ^ 0x1BD11BDAu;
    unsigned x0 = c0 + ks0;
    unsigned x1 = c1 + ks1;
#define TF_ROUND(r) { x0 += x1; x1 = rotl32(x1, r); x1 ^= x0; }
    TF_ROUND(13) TF_ROUND(15) TF_ROUND(26) TF_ROUND(6)
    x0 += ks1; x1 += ks2 + 1u;
    TF_ROUND(17) TF_ROUND(29) TF_ROUND(16) TF_ROUND(24)
    x0 += ks2; x1 += ks0 + 2u;
    TF_ROUND(13) TF_ROUND(15) TF_ROUND(26) TF_ROUND(6)
    x0 += ks0; x1 += ks1 + 3u;
    TF_ROUND(17) TF_ROUND(29) TF_ROUND(16) TF_ROUND(24)
    x0 += ks1; x1 += ks2 + 4u;
    TF_ROUND(13) TF_ROUND(15) TF_ROUND(26) TF_ROUND(6)
    x0 += ks2; x1 += ks0 + 5u;
#undef TF_ROUND
    return make_uint2(x0, x1);
}
__device__ __forceinline__ float jax_gumbel(unsigned i) {
    uint2 r = threefry_0_42(0u, i);
    unsigned bits = r.x ^ r.y;
    float f = __uint_as_float((bits >> 9) | 0x3f800000u) - 1.0f;
    float u = (f == 0.0f) ? 1.17549435e-38f : f;
    return -logf(-logf(u));
}

#define NCAND 2048
#define RANK  1000
#define NF4P  (VP / 4)       /* 12576: full padded row, no bounds checks */

__global__ __launch_bounds__(1024) void sample_kernel(
    const float* __restrict__ top_ps,
    const int*   __restrict__ top_ks,
    float* __restrict__ out_ids,
    float* __restrict__ out_lp,
    float* __restrict__ out_fprobs)
{
    const int b    = blockIdx.x;
    const int t    = threadIdx.x;
    const int lane = t & 31;
    const int wid  = t >> 5;
    const float* row = g_logits + (size_t)b * VP;
    const float4* row4 = reinterpret_cast<const float4*>(row);
    float* fp = out_fprobs + (size_t)b * VOCAB;
    int* gh = g_hist + b * 2048;

    const float logZ = logf(g_sums[b]);

    __shared__ unsigned long long s_keys[NCAND];
    __shared__ unsigned long long s_sel[NCAND];
    __shared__ int   s_hist[2048];
    __shared__ float s_wred[32];
    __shared__ int   s_widx[32];
    __shared__ int   s_sel1, s_rank2, s_sel2, s_cntHi, s_cntSel;

    // load global hist, then zero it for next replay
    for (int i = t; i < 2048; i += 1024) {
        s_hist[i] = gh[i];
        gh[i] = 0;
    }
    if (t == 0) { s_cntHi = 0; s_cntSel = 0; }
    __syncthreads();

    // warp 0: suffix-scan for sel1/rank2
    if (wid == 0) {
        int acc = 0;
        for (int base = 2048 - 32; base >= 0; base -= 32) {
            int bin = base + 31 - lane;
            int c = s_hist[bin];
            int p = c;
            for (int o = 1; o < 32; o <<= 1) {
                int v = __shfl_up_sync(0xffffffffu, p, o);
                if (lane >= o) p += v;
            }
            int S = acc + p;
            unsigned msk = __ballot_sync(0xffffffffu, S >= RANK);
            if (msk) {
                int l = __ffs(msk) - 1;
                int Ssel = __shfl_sync(0xffffffffu, S, l);
                int csel = __shfl_sync(0xffffffffu, c, l);
                if (lane == 0) {
                    s_sel1  = base + 31 - l;
                    s_rank2 = RANK - (Ssel - csel);
                }
                break;
            }
            acc += __shfl_sync(0xffffffffu, p, 31);
        }
    }
    __syncthreads();
    const int sel1 = s_sel1;
    const int rank2 = s_rank2;

    for (int i = t; i < 2048; i += 1024) s_hist[i] = 0;
    __syncthreads();

    // ---- single collect pass over padded row (pads are -inf, bin 3) ----
    for (int i4 = t; i4 < NF4P; i4 += 1024) {
        float4 v = row4[i4];
        int gi = i4 * 4;
        float e[4] = {v.x, v.y, v.z, v.w};
#pragma unroll
        for (int j = 0; j < 4; j++) {
            unsigned k = fmap(e[j]);
            int top11 = (int)(k >> 21);
            if (top11 > sel1) {
                int pos = atomicAdd(&s_cntHi, 1);   // bounded by RANK-1
                s_keys[pos] = ((unsigned long long)(~k) << 32) | (unsigned)(gi + j);
            } else if (top11 == sel1) {
                atomicAdd(&s_hist[(k >> 10) & 0x7FF], 1);
                int pos = atomicAdd(&s_cntSel, 1);
                if (pos < NCAND)
                    s_sel[pos] = ((unsigned long long)(~k) << 32) | (unsigned)(gi + j);
            }
        }
    }
    __syncthreads();

    // warp 0: suffix-scan for sel2
    if (wid == 0) {
        int acc = 0;
        for (int base = 2048 - 32; base >= 0; base -= 32) {
            int bin = base + 31 - lane;
            int c = s_hist[bin];
            int p = c;
            for (int o = 1; o < 32; o <<= 1) {
                int v = __shfl_up_sync(0xffffffffu, p, o);
                if (lane >= o) p += v;
            }
            int S = acc + p;
            unsigned msk = __ballot_sync(0xffffffffu, S >= rank2);
            if (msk) {
                int l = __ffs(msk) - 1;
                if (lane == 0) s_sel2 = base + 31 - l;
                break;
            }
            acc += __shfl_sync(0xffffffffu, p, 31);
        }
    }
    __syncthreads();
    const int sel2 = s_sel2;

    // ---- append sel-bucket keys with second-level bin >= sel2 ----
    int cntSel = s_cntSel; if (cntSel > NCAND) cntSel = NCAND;
    for (int i = t; i < cntSel; i += 1024) {
        unsigned long long key = s_sel[i];
        unsigned k = ~(unsigned)(key >> 32);
        if ((int)((k >> 10) & 0x7FF) >= sel2) {
            int pos = atomicAdd(&s_cntHi, 1);
            if (pos < NCAND) s_keys[pos] = key;
        }
    }
    __syncthreads();
    int cnt = s_cntHi; if (cnt > NCAND) cnt = NCAND;
    const int N = (cnt <= 1024) ? 1024 : NCAND;
    for (int i = t; i < N; i += 1024)
        if (i >= cnt) s_keys[i] = 0xFFFFFFFFFFFFFFFFull;
    __syncthreads();

    // ---- bitonic sort ascending (=> descending logit, stable ties) ----
    for (int k = 2; k <= N; k <<= 1) {
        for (int j = k >> 1; j > 0; j >>= 1) {
            for (int i = t; i < N; i += 1024) {
                int ixj = i ^ j;
                if (ixj > i) {
                    unsigned long long a = s_keys[i], c2 = s_keys[ixj];
                    bool asc = ((i & k) == 0);
                    if (asc ? (a > c2) : (a < c2)) {
                        s_keys[i] = c2;
                        s_keys[ixj] = a;
                    }
                }
            }
            __syncthreads();
        }
    }

    // ---- parallel top-p/top-k mask ----
    const int   K  = top_ks[b];
    const float tp = top_ps[b];
    const int limit = (cnt < K ? cnt : K);       // <= 999 < 1024

    float p = 0.f;
    int   idx = 0;
    const bool valid = (t < limit);
    if (valid) {
        unsigned long long key = s_keys[t];
        unsigned hi = (unsigned)(key >> 32);
        float logit = funmap(~hi);
        idx = (int)(unsigned)(key & 0xFFFFFFFFull);
        p = expf(logit - logZ);
    }
    // block-wide exclusive scan of p
    float x = p;
    for (int o = 1; o < 32; o <<= 1) {
        float v = __shfl_up_sync(0xffffffffu, x, o);
        if (lane >= o) x += v;
    }
    if (lane == 31) s_wred[wid] = x;
    __syncthreads();
    if (wid == 0) {
        float w = s_wred[lane];
        float y = w;
        for (int o = 1; o < 32; o <<= 1) {
            float v = __shfl_up_sync(0xffffffffu, y, o);
            if (lane >= o) y += v;
        }
        s_wred[lane] = y - w;
    }
    __syncthreads();
    float excl = s_wred[wid] + x - p;
    const bool survive = valid && (excl <= tp);

    // ---- scatter fprobs + gumbel argmax over survivors ----
    float best  = NEGINF;
    int   bestv = 0x7fffffff;
    if (survive) {
        fp[idx] = p;
        float g = jax_gumbel((unsigned)(b * VOCAB + idx));
        best  = logf(p) + g;
        bestv = idx;
    }
#pragma unroll
    for (int o = 16; o > 0; o >>= 1) {
        float ob = __shfl_xor_sync(0xffffffffu, best, o);
        int   ov = __shfl_xor_sync(0xffffffffu, bestv, o);
        if (ob > best || (ob == best && ov < bestv)) { best = ob; bestv = ov; }
    }
    if (lane == 0) { s_wred[wid] = best; s_widx[wid] = bestv; }
    __syncthreads();
    if (wid == 0) {
        best  = s_wred[lane];
        bestv = s_widx[lane];
#pragma unroll
        for (int o = 16; o > 0; o >>= 1) {
            float ob = __shfl_xor_sync(0xffffffffu, best, o);
            int   ov = __shfl_xor_sync(0xffffffffu, bestv, o);
            if (ob > best || (ob == best && ov < bestv)) { best = ob; bestv = ov; }
        }
        if (lane == 0) {
            out_ids[b] = (float)bestv;
            out_lp[b]  = row[bestv] - logZ;
            g_sums[b]  = 0.0f;   // reset for next graph replay
        }
    }
}

// =========================================================================
// launch
// =========================================================================
extern "C" void kernel_launch(void* const* d_in, const int* in_sizes, int n_in,
                              void* d_out, int out_size) {
    const float* H     = (const float*)d_in[0];
    const float* E     = (const float*)d_in[1];
    const float* temps = (const float*)d_in[2];
    const float* tps   = (const float*)d_in[3];
    const int*   tks   = (const int*)d_in[4];

    float* out = (float*)d_out;
    int fbase = out_size - BATCH * VOCAB;
    if (fbase < 0) fbase = 0;
    float* out_ids = out;
    float* out_lp  = out + ((fbase >= 2 * BATCH) ? BATCH : 0);
    float* out_fp  = out + fbase;

    cudaFuncSetAttribute(gemm_hmma_kernel,
                         cudaFuncAttributeMaxDynamicSharedMemorySize, GSMEM);

    gemm_hmma_kernel<<<(VOCAB + TN - 1) / TN, 256, GSMEM>>>(H, E, temps);
    hist_kernel<<<dim3(NSLICE, BATCH), 1024>>>(out_fp);
    sample_kernel<<<BATCH, 1024>>>(tps, tks, out_ids, out_lp, out_fp);
}